// round 1
// baseline (speedup 1.0000x reference)
#include <cuda_runtime.h>
#include <cuda_bf16.h>
#include <math.h>

// Problem constants
#define BATCH 4
#define SEQ   2048
#define NH    16
#define HD    64
#define HID   1024           // NH*HD
#define MROWS (BATCH*SEQ)    // 8192

// ---------------------------------------------------------------------------
// Scratch (allocation-free): q, k, v, attn_out, each [MROWS, HID] fp32
// ---------------------------------------------------------------------------
__device__ float g_q[MROWS * HID];
__device__ float g_k[MROWS * HID];
__device__ float g_v[MROWS * HID];
__device__ float g_attn[MROWS * HID];

// ---------------------------------------------------------------------------
// SGEMM: C[m,n] = sum_k A[m,k] * B[n,k]   (A: MxK row-major, B: NxK row-major)
// 128x128 block, K-tile 8, 256 threads, 8x8 per-thread micro-tile (split 4+4)
// ---------------------------------------------------------------------------
__global__ void __launch_bounds__(256) sgemm_nt(const float* __restrict__ A,
                                                const float* __restrict__ B,
                                                float* __restrict__ C,
                                                int M, int N, int K) {
    __shared__ float As[8][128];
    __shared__ float Bs[8][128];

    const int tid = threadIdx.x;
    const int tx = tid & 15;
    const int ty = tid >> 4;
    const int lrow = tid >> 1;        // 0..127
    const int lcol = (tid & 1) * 4;   // 0 or 4

    const float* Ag = A + (size_t)(blockIdx.y * 128 + lrow) * K + lcol;
    const float* Bg = B + (size_t)(blockIdx.x * 128 + lrow) * K + lcol;

    float acc[8][8];
#pragma unroll
    for (int i = 0; i < 8; i++)
#pragma unroll
        for (int j = 0; j < 8; j++) acc[i][j] = 0.f;

    for (int k0 = 0; k0 < K; k0 += 8) {
        float4 a4 = *reinterpret_cast<const float4*>(Ag + k0);
        float4 b4 = *reinterpret_cast<const float4*>(Bg + k0);
        As[lcol + 0][lrow] = a4.x; As[lcol + 1][lrow] = a4.y;
        As[lcol + 2][lrow] = a4.z; As[lcol + 3][lrow] = a4.w;
        Bs[lcol + 0][lrow] = b4.x; Bs[lcol + 1][lrow] = b4.y;
        Bs[lcol + 2][lrow] = b4.z; Bs[lcol + 3][lrow] = b4.w;
        __syncthreads();

#pragma unroll
        for (int kk = 0; kk < 8; kk++) {
            float ar[8], br[8];
            *reinterpret_cast<float4*>(&ar[0]) =
                *reinterpret_cast<float4*>(&As[kk][ty * 4]);
            *reinterpret_cast<float4*>(&ar[4]) =
                *reinterpret_cast<float4*>(&As[kk][64 + ty * 4]);
            *reinterpret_cast<float4*>(&br[0]) =
                *reinterpret_cast<float4*>(&Bs[kk][tx * 4]);
            *reinterpret_cast<float4*>(&br[4]) =
                *reinterpret_cast<float4*>(&Bs[kk][64 + tx * 4]);
#pragma unroll
            for (int i = 0; i < 8; i++)
#pragma unroll
                for (int j = 0; j < 8; j++) acc[i][j] += ar[i] * br[j];
        }
        __syncthreads();
    }

    // Write back: rows {ty*4..+3, 64+ty*4..+3}, cols {tx*4..+3, 64+tx*4..+3}
#pragma unroll
    for (int ih = 0; ih < 2; ih++) {
#pragma unroll
        for (int i = 0; i < 4; i++) {
            int r = blockIdx.y * 128 + ih * 64 + ty * 4 + i;
            float4 v0 = make_float4(acc[ih * 4 + i][0], acc[ih * 4 + i][1],
                                    acc[ih * 4 + i][2], acc[ih * 4 + i][3]);
            float4 v1 = make_float4(acc[ih * 4 + i][4], acc[ih * 4 + i][5],
                                    acc[ih * 4 + i][6], acc[ih * 4 + i][7]);
            *reinterpret_cast<float4*>(C + (size_t)r * N + blockIdx.x * 128 + tx * 4) = v0;
            *reinterpret_cast<float4*>(C + (size_t)r * N + blockIdx.x * 128 + 64 + tx * 4) = v1;
        }
    }
}

// ---------------------------------------------------------------------------
// RoPE (in-place): for each (row m, head h, d<32):
//   out[d]    = x[d]*cos - x[d+32]*sin
//   out[d+32] = x[d+32]*cos + x[d]*sin      (cos[t,d]==cos[t,d+32])
// ---------------------------------------------------------------------------
__global__ void rope_kernel(float* __restrict__ qk,
                            const float* __restrict__ cosT,
                            const float* __restrict__ sinT) {
    int idx = blockIdx.x * blockDim.x + threadIdx.x;
    if (idx >= MROWS * NH * 32) return;
    int d = idx & 31;
    int h = (idx >> 5) & (NH - 1);
    int m = idx >> 9;              // / (NH*32)
    int t = m & (SEQ - 1);
    float c = cosT[t * HD + d];
    float s = sinT[t * HD + d];
    size_t base = (size_t)m * HID + h * HD + d;
    float x1 = qk[base];
    float x2 = qk[base + 32];
    qk[base]      = x1 * c - x2 * s;
    qk[base + 32] = x2 * c + x1 * s;
}

// ---------------------------------------------------------------------------
// Flash attention, fp32, causal. One block = one (b,h) x 64-query tile.
// q,k,v layout: [MROWS, HID]; for fixed (b,h): row stride HID, 64 contiguous.
// smem: Qt[d][q] (d-major), Kt[d][k], Vs[k][d], Ps[q][65], m/l/corr[64]
// ---------------------------------------------------------------------------
#define FLASH_SMEM ((3 * 64 * 64 + 64 * 65 + 3 * 64) * sizeof(float))

__global__ void __launch_bounds__(256) flash_attn(const float* __restrict__ q,
                                                  const float* __restrict__ k,
                                                  const float* __restrict__ v,
                                                  float* __restrict__ o) {
    extern __shared__ float sm[];
    float* Qt   = sm;                 // [64][64]
    float* Kt   = Qt + 64 * 64;       // [64][64]
    float* Vs   = Kt + 64 * 64;       // [64][64]
    float* Ps   = Vs + 64 * 64;       // [64][65]
    float* mrow = Ps + 64 * 65;       // [64]
    float* lrow = mrow + 64;          // [64]
    float* crow = lrow + 64;          // [64]

    const int qt = blockIdx.x;        // query tile
    const int bh = blockIdx.y;
    const int b = bh >> 4;            // / NH
    const int h = bh & 15;
    const int tid = threadIdx.x;
    const int tx = tid & 15;
    const int ty = tid >> 4;

    const size_t baseQ  = ((size_t)b * SEQ + qt * 64) * HID + h * HD;
    const size_t baseKV = (size_t)b * SEQ * HID + h * HD;

    // Load Q tile transposed: Qt[d][qr]
    for (int e = tid; e < 64 * 16; e += 256) {
        int r = e >> 4;
        int c = (e & 15) * 4;
        float4 val = *reinterpret_cast<const float4*>(q + baseQ + (size_t)r * HID + c);
        Qt[(c + 0) * 64 + r] = val.x; Qt[(c + 1) * 64 + r] = val.y;
        Qt[(c + 2) * 64 + r] = val.z; Qt[(c + 3) * 64 + r] = val.w;
    }
    if (tid < 64) { mrow[tid] = -INFINITY; lrow[tid] = 0.f; }

    float accO[4][4];
#pragma unroll
    for (int i = 0; i < 4; i++)
#pragma unroll
        for (int j = 0; j < 4; j++) accO[i][j] = 0.f;

    __syncthreads();

    for (int jt = 0; jt <= qt; jt++) {
        // Load K tile (transposed) and V tile (row-major)
        const float* kb = k + baseKV + (size_t)jt * 64 * HID;
        const float* vb = v + baseKV + (size_t)jt * 64 * HID;
        for (int e = tid; e < 64 * 16; e += 256) {
            int r = e >> 4;
            int c = (e & 15) * 4;
            float4 kv = *reinterpret_cast<const float4*>(kb + (size_t)r * HID + c);
            Kt[(c + 0) * 64 + r] = kv.x; Kt[(c + 1) * 64 + r] = kv.y;
            Kt[(c + 2) * 64 + r] = kv.z; Kt[(c + 3) * 64 + r] = kv.w;
            *reinterpret_cast<float4*>(&Vs[r * 64 + c]) =
                *reinterpret_cast<const float4*>(vb + (size_t)r * HID + c);
        }
        __syncthreads();

        // S = Q K^T (64x64), per-thread 4x4 micro-tile
        float accS[4][4];
#pragma unroll
        for (int i = 0; i < 4; i++)
#pragma unroll
            for (int j = 0; j < 4; j++) accS[i][j] = 0.f;

#pragma unroll 16
        for (int d = 0; d < 64; d++) {
            float a[4], bb[4];
            *reinterpret_cast<float4*>(a)  = *reinterpret_cast<float4*>(&Qt[d * 64 + ty * 4]);
            *reinterpret_cast<float4*>(bb) = *reinterpret_cast<float4*>(&Kt[d * 64 + tx * 4]);
#pragma unroll
            for (int i = 0; i < 4; i++)
#pragma unroll
                for (int j = 0; j < 4; j++) accS[i][j] += a[i] * bb[j];
        }

        // scale + causal mask + spill to Ps
        const float scale = 0.125f;  // 1/sqrt(64)
        const bool diag = (jt == qt);
#pragma unroll
        for (int i = 0; i < 4; i++) {
#pragma unroll
            for (int j = 0; j < 4; j++) {
                float s = accS[i][j] * scale;
                if (diag && (tx * 4 + j) > (ty * 4 + i)) s = -INFINITY;
                Ps[(ty * 4 + i) * 65 + tx * 4 + j] = s;
            }
        }
        __syncthreads();

        // Online softmax: one thread per query row
        if (tid < 64) {
            float* pr = &Ps[tid * 65];
            float mo = mrow[tid];
            float mn = mo;
#pragma unroll 8
            for (int c = 0; c < 64; c++) mn = fmaxf(mn, pr[c]);
            float corr = expf(mo - mn);
            float sum = 0.f;
#pragma unroll 8
            for (int c = 0; c < 64; c++) {
                float p = expf(pr[c] - mn);
                pr[c] = p;
                sum += p;
            }
            mrow[tid] = mn;
            lrow[tid] = lrow[tid] * corr + sum;
            crow[tid] = corr;
        }
        __syncthreads();

        // Rescale O, then O += P @ V
        float cr[4];
#pragma unroll
        for (int i = 0; i < 4; i++) cr[i] = crow[ty * 4 + i];
#pragma unroll
        for (int i = 0; i < 4; i++)
#pragma unroll
            for (int j = 0; j < 4; j++) accO[i][j] *= cr[i];

#pragma unroll 16
        for (int kk = 0; kk < 64; kk++) {
            float a[4], bb[4];
#pragma unroll
            for (int i = 0; i < 4; i++) a[i] = Ps[(ty * 4 + i) * 65 + kk];
            *reinterpret_cast<float4*>(bb) = *reinterpret_cast<float4*>(&Vs[kk * 64 + tx * 4]);
#pragma unroll
            for (int i = 0; i < 4; i++)
#pragma unroll
                for (int j = 0; j < 4; j++) accO[i][j] += a[i] * bb[j];
        }
        __syncthreads();
    }

    // Normalize and write: attn_out[b, t, h*64 + d]
#pragma unroll
    for (int i = 0; i < 4; i++) {
        int qrow = qt * 64 + ty * 4 + i;
        float inv = 1.f / lrow[ty * 4 + i];
        float4 val = make_float4(accO[i][0] * inv, accO[i][1] * inv,
                                 accO[i][2] * inv, accO[i][3] * inv);
        *reinterpret_cast<float4*>(o + ((size_t)b * SEQ + qrow) * HID + h * HD + tx * 4) = val;
    }
}

// ---------------------------------------------------------------------------
// Launch
// ---------------------------------------------------------------------------
extern "C" void kernel_launch(void* const* d_in, const int* in_sizes, int n_in,
                              void* d_out, int out_size) {
    const float* x    = (const float*)d_in[0];
    const float* cosT = (const float*)d_in[1];
    const float* sinT = (const float*)d_in[2];
    const float* wq   = (const float*)d_in[3];
    const float* wk   = (const float*)d_in[4];
    const float* wv   = (const float*)d_in[5];
    const float* wo   = (const float*)d_in[6];
    float* out = (float*)d_out;

    float *q, *k, *v, *attn;
    cudaGetSymbolAddress((void**)&q, g_q);
    cudaGetSymbolAddress((void**)&k, g_k);
    cudaGetSymbolAddress((void**)&v, g_v);
    cudaGetSymbolAddress((void**)&attn, g_attn);

    dim3 gemm_grid(HID / 128, MROWS / 128);   // (8, 64)
    sgemm_nt<<<gemm_grid, 256>>>(x, wq, q, MROWS, HID, HID);
    sgemm_nt<<<gemm_grid, 256>>>(x, wk, k, MROWS, HID, HID);
    sgemm_nt<<<gemm_grid, 256>>>(x, wv, v, MROWS, HID, HID);

    int rope_n = MROWS * NH * 32;
    rope_kernel<<<(rope_n + 255) / 256, 256>>>(q, cosT, sinT);
    rope_kernel<<<(rope_n + 255) / 256, 256>>>(k, cosT, sinT);

    cudaFuncSetAttribute(flash_attn, cudaFuncAttributeMaxDynamicSharedMemorySize,
                         (int)FLASH_SMEM);
    dim3 fgrid(SEQ / 64, BATCH * NH);         // (32, 64)
    flash_attn<<<fgrid, 256, FLASH_SMEM>>>(q, k, v, attn);

    sgemm_nt<<<gemm_grid, 256>>>(attn, wo, out, MROWS, HID, HID);
}

// round 2
// speedup vs baseline: 1.0409x; 1.0409x over previous
#include <cuda_runtime.h>
#include <cuda_bf16.h>
#include <math.h>

// Problem constants
#define BATCH 4
#define SEQ   2048
#define NH    16
#define HD    64
#define HID   1024           // NH*HD
#define MROWS (BATCH*SEQ)    // 8192

typedef unsigned long long ull;

// ---------------------------------------------------------------------------
// Packed f32x2 helpers (Blackwell sm_103a): 2 fp32 FMAs per instruction.
// ---------------------------------------------------------------------------
__device__ __forceinline__ ull pack2(float lo, float hi) {
    ull r;
    asm("mov.b64 %0, {%1, %2};" : "=l"(r) : "f"(lo), "f"(hi));
    return r;
}
__device__ __forceinline__ void unpack2(ull v, float& lo, float& hi) {
    asm("mov.b64 {%0, %1}, %2;" : "=f"(lo), "=f"(hi) : "l"(v));
}
__device__ __forceinline__ void fma2(ull& d, ull a, ull b) {
    asm("fma.rn.f32x2 %0, %1, %2, %3;" : "=l"(d) : "l"(a), "l"(b), "l"(d));
}
__device__ __forceinline__ void mul2(ull& d, ull a, ull b) {
    asm("mul.rn.f32x2 %0, %1, %2;" : "=l"(d) : "l"(a), "l"(b));
}

// ---------------------------------------------------------------------------
// Scratch (allocation-free): q, k, v, attn_out, each [MROWS, HID] fp32
// ---------------------------------------------------------------------------
__device__ float g_q[MROWS * HID];
__device__ float g_k[MROWS * HID];
__device__ float g_v[MROWS * HID];
__device__ float g_attn[MROWS * HID];

// ---------------------------------------------------------------------------
// SGEMM: C[m,n] = sum_k A[m,k] * B[n,k]   (A: MxK row-major, B: NxK row-major)
// 128x128 block, K-tile 8, 256 threads, 8x8 per-thread micro-tile (split 4+4)
// Inner product uses packed f32x2 FMA (2x fp32 throughput vs scalar FFMA).
// ---------------------------------------------------------------------------
__global__ void __launch_bounds__(256) sgemm_nt(const float* __restrict__ A,
                                                const float* __restrict__ B,
                                                float* __restrict__ C,
                                                int M, int N, int K) {
    __shared__ float As[8][128];
    __shared__ float Bs[8][128];

    const int tid = threadIdx.x;
    const int tx = tid & 15;
    const int ty = tid >> 4;
    const int lrow = tid >> 1;        // 0..127
    const int lcol = (tid & 1) * 4;   // 0 or 4

    const float* Ag = A + (size_t)(blockIdx.y * 128 + lrow) * K + lcol;
    const float* Bg = B + (size_t)(blockIdx.x * 128 + lrow) * K + lcol;

    // acc2[i][j2]: row i (of 8), packed col pair j2 (of 4) => 8x8 fp32 tile
    ull acc2[8][4];
    const ull zz = pack2(0.f, 0.f);
#pragma unroll
    for (int i = 0; i < 8; i++)
#pragma unroll
        for (int j = 0; j < 4; j++) acc2[i][j] = zz;

    for (int k0 = 0; k0 < K; k0 += 8) {
        float4 a4 = *reinterpret_cast<const float4*>(Ag + k0);
        float4 b4 = *reinterpret_cast<const float4*>(Bg + k0);
        As[lcol + 0][lrow] = a4.x; As[lcol + 1][lrow] = a4.y;
        As[lcol + 2][lrow] = a4.z; As[lcol + 3][lrow] = a4.w;
        Bs[lcol + 0][lrow] = b4.x; Bs[lcol + 1][lrow] = b4.y;
        Bs[lcol + 2][lrow] = b4.z; Bs[lcol + 3][lrow] = b4.w;
        __syncthreads();

#pragma unroll
        for (int kk = 0; kk < 8; kk++) {
            float4 af0 = *reinterpret_cast<float4*>(&As[kk][ty * 4]);
            float4 af1 = *reinterpret_cast<float4*>(&As[kk][64 + ty * 4]);
            float4 bf0 = *reinterpret_cast<float4*>(&Bs[kk][tx * 4]);
            float4 bf1 = *reinterpret_cast<float4*>(&Bs[kk][64 + tx * 4]);
            float ar[8] = {af0.x, af0.y, af0.z, af0.w, af1.x, af1.y, af1.z, af1.w};
            ull b2[4];
            b2[0] = *reinterpret_cast<ull*>(&bf0.x);
            b2[1] = *reinterpret_cast<ull*>(&bf0.z);
            b2[2] = *reinterpret_cast<ull*>(&bf1.x);
            b2[3] = *reinterpret_cast<ull*>(&bf1.z);
#pragma unroll
            for (int i = 0; i < 8; i++) {
                ull a2 = pack2(ar[i], ar[i]);
#pragma unroll
                for (int j = 0; j < 4; j++) fma2(acc2[i][j], a2, b2[j]);
            }
        }
        __syncthreads();
    }

    // Write back
#pragma unroll
    for (int ih = 0; ih < 2; ih++) {
#pragma unroll
        for (int i = 0; i < 4; i++) {
            int r = blockIdx.y * 128 + ih * 64 + ty * 4 + i;
            float c0, c1, c2, c3, c4, c5, c6, c7;
            unpack2(acc2[ih * 4 + i][0], c0, c1);
            unpack2(acc2[ih * 4 + i][1], c2, c3);
            unpack2(acc2[ih * 4 + i][2], c4, c5);
            unpack2(acc2[ih * 4 + i][3], c6, c7);
            *reinterpret_cast<float4*>(C + (size_t)r * N + blockIdx.x * 128 + tx * 4) =
                make_float4(c0, c1, c2, c3);
            *reinterpret_cast<float4*>(C + (size_t)r * N + blockIdx.x * 128 + 64 + tx * 4) =
                make_float4(c4, c5, c6, c7);
        }
    }
}

// ---------------------------------------------------------------------------
// RoPE (in-place)
// ---------------------------------------------------------------------------
__global__ void rope_kernel(float* __restrict__ qk,
                            const float* __restrict__ cosT,
                            const float* __restrict__ sinT) {
    int idx = blockIdx.x * blockDim.x + threadIdx.x;
    if (idx >= MROWS * NH * 32) return;
    int d = idx & 31;
    int h = (idx >> 5) & (NH - 1);
    int m = idx >> 9;
    int t = m & (SEQ - 1);
    float c = cosT[t * HD + d];
    float s = sinT[t * HD + d];
    size_t base = (size_t)m * HID + h * HD + d;
    float x1 = qk[base];
    float x2 = qk[base + 32];
    qk[base]      = x1 * c - x2 * s;
    qk[base + 32] = x2 * c + x1 * s;
}

// ---------------------------------------------------------------------------
// Flash attention, fp32, causal. One block = one (b,h) x 64-query tile.
// Inner GEMMs use packed f32x2 FMA; softmax uses 4 threads/row + __expf.
// ---------------------------------------------------------------------------
#define FLASH_SMEM ((3 * 64 * 64 + 64 * 65 + 3 * 64) * sizeof(float))

__global__ void __launch_bounds__(256) flash_attn(const float* __restrict__ q,
                                                  const float* __restrict__ k,
                                                  const float* __restrict__ v,
                                                  float* __restrict__ o) {
    extern __shared__ float sm[];
    float* Qt   = sm;                 // [64][64] d-major
    float* Kt   = Qt + 64 * 64;       // [64][64] d-major
    float* Vs   = Kt + 64 * 64;       // [64][64] row-major
    float* Ps   = Vs + 64 * 64;       // [64][65]
    float* mrow = Ps + 64 * 65;       // [64]
    float* lrow = mrow + 64;          // [64]
    float* crow = lrow + 64;          // [64]

    const int qt = blockIdx.x;
    const int bh = blockIdx.y;
    const int b = bh >> 4;
    const int h = bh & 15;
    const int tid = threadIdx.x;
    const int tx = tid & 15;
    const int ty = tid >> 4;

    const size_t baseQ  = ((size_t)b * SEQ + qt * 64) * HID + h * HD;
    const size_t baseKV = (size_t)b * SEQ * HID + h * HD;

    // Load Q tile transposed
    for (int e = tid; e < 64 * 16; e += 256) {
        int r = e >> 4;
        int c = (e & 15) * 4;
        float4 val = *reinterpret_cast<const float4*>(q + baseQ + (size_t)r * HID + c);
        Qt[(c + 0) * 64 + r] = val.x; Qt[(c + 1) * 64 + r] = val.y;
        Qt[(c + 2) * 64 + r] = val.z; Qt[(c + 3) * 64 + r] = val.w;
    }
    if (tid < 64) { mrow[tid] = -INFINITY; lrow[tid] = 0.f; }

    ull accO2[4][2];
    const ull zz = pack2(0.f, 0.f);
#pragma unroll
    for (int i = 0; i < 4; i++) { accO2[i][0] = zz; accO2[i][1] = zz; }

    __syncthreads();

    for (int jt = 0; jt <= qt; jt++) {
        const float* kb = k + baseKV + (size_t)jt * 64 * HID;
        const float* vb = v + baseKV + (size_t)jt * 64 * HID;
        for (int e = tid; e < 64 * 16; e += 256) {
            int r = e >> 4;
            int c = (e & 15) * 4;
            float4 kv = *reinterpret_cast<const float4*>(kb + (size_t)r * HID + c);
            Kt[(c + 0) * 64 + r] = kv.x; Kt[(c + 1) * 64 + r] = kv.y;
            Kt[(c + 2) * 64 + r] = kv.z; Kt[(c + 3) * 64 + r] = kv.w;
            *reinterpret_cast<float4*>(&Vs[r * 64 + c]) =
                *reinterpret_cast<const float4*>(vb + (size_t)r * HID + c);
        }
        __syncthreads();

        // S = Q K^T (64x64), per-thread 4x4 micro-tile, f32x2
        ull accS2[4][2];
#pragma unroll
        for (int i = 0; i < 4; i++) { accS2[i][0] = zz; accS2[i][1] = zz; }

#pragma unroll 8
        for (int d = 0; d < 64; d++) {
            float4 af = *reinterpret_cast<float4*>(&Qt[d * 64 + ty * 4]);
            float4 bf = *reinterpret_cast<float4*>(&Kt[d * 64 + tx * 4]);
            ull b2[2];
            b2[0] = *reinterpret_cast<ull*>(&bf.x);
            b2[1] = *reinterpret_cast<ull*>(&bf.z);
            float ar[4] = {af.x, af.y, af.z, af.w};
#pragma unroll
            for (int i = 0; i < 4; i++) {
                ull a2 = pack2(ar[i], ar[i]);
                fma2(accS2[i][0], a2, b2[0]);
                fma2(accS2[i][1], a2, b2[1]);
            }
        }

        // scale + causal mask + spill to Ps
        const float scale = 0.125f;  // 1/sqrt(64)
        const bool diag = (jt == qt);
#pragma unroll
        for (int i = 0; i < 4; i++) {
            float s0, s1, s2, s3;
            unpack2(accS2[i][0], s0, s1);
            unpack2(accS2[i][1], s2, s3);
            float sv[4] = {s0, s1, s2, s3};
#pragma unroll
            for (int j = 0; j < 4; j++) {
                float s = sv[j] * scale;
                if (diag && (tx * 4 + j) > (ty * 4 + i)) s = -INFINITY;
                Ps[(ty * 4 + i) * 65 + tx * 4 + j] = s;
            }
        }
        __syncthreads();

        // Online softmax: 4 threads per query row (shfl combine within warp).
        {
            int r  = tid >> 2;        // 0..63
            int qd = tid & 3;         // quadrant: cols qd*16..qd*16+15
            float* pr = &Ps[r * 65 + qd * 16];
            float mo = mrow[r];
            float m4 = -INFINITY;
#pragma unroll
            for (int c = 0; c < 16; c++) m4 = fmaxf(m4, pr[c]);
            m4 = fmaxf(m4, __shfl_xor_sync(0xFFFFFFFF, m4, 1));
            m4 = fmaxf(m4, __shfl_xor_sync(0xFFFFFFFF, m4, 2));
            float mn = fmaxf(mo, m4);
            float sum = 0.f;
#pragma unroll
            for (int c = 0; c < 16; c++) {
                float p = __expf(pr[c] - mn);
                pr[c] = p;
                sum += p;
            }
            sum += __shfl_xor_sync(0xFFFFFFFF, sum, 1);
            sum += __shfl_xor_sync(0xFFFFFFFF, sum, 2);
            if (qd == 0) {
                float corr = __expf(mo - mn);
                mrow[r] = mn;
                lrow[r] = lrow[r] * corr + sum;
                crow[r] = corr;
            }
        }
        __syncthreads();

        // Rescale O, then O += P @ V  (f32x2)
#pragma unroll
        for (int i = 0; i < 4; i++) {
            ull c2 = pack2(crow[ty * 4 + i], crow[ty * 4 + i]);
            mul2(accO2[i][0], accO2[i][0], c2);
            mul2(accO2[i][1], accO2[i][1], c2);
        }

#pragma unroll 8
        for (int kk = 0; kk < 64; kk++) {
            float4 bf = *reinterpret_cast<float4*>(&Vs[kk * 64 + tx * 4]);
            ull b2[2];
            b2[0] = *reinterpret_cast<ull*>(&bf.x);
            b2[1] = *reinterpret_cast<ull*>(&bf.z);
#pragma unroll
            for (int i = 0; i < 4; i++) {
                ull a2 = pack2(Ps[(ty * 4 + i) * 65 + kk], Ps[(ty * 4 + i) * 65 + kk]);
                fma2(accO2[i][0], a2, b2[0]);
                fma2(accO2[i][1], a2, b2[1]);
            }
        }
        __syncthreads();
    }

    // Normalize and write
#pragma unroll
    for (int i = 0; i < 4; i++) {
        int qrow = qt * 64 + ty * 4 + i;
        float inv = 1.f / lrow[ty * 4 + i];
        float o0, o1, o2, o3;
        unpack2(accO2[i][0], o0, o1);
        unpack2(accO2[i][1], o2, o3);
        float4 val = make_float4(o0 * inv, o1 * inv, o2 * inv, o3 * inv);
        *reinterpret_cast<float4*>(o + ((size_t)b * SEQ + qrow) * HID + h * HD + tx * 4) = val;
    }
}

// ---------------------------------------------------------------------------
// Launch
// ---------------------------------------------------------------------------
extern "C" void kernel_launch(void* const* d_in, const int* in_sizes, int n_in,
                              void* d_out, int out_size) {
    const float* x    = (const float*)d_in[0];
    const float* cosT = (const float*)d_in[1];
    const float* sinT = (const float*)d_in[2];
    const float* wq   = (const float*)d_in[3];
    const float* wk   = (const float*)d_in[4];
    const float* wv   = (const float*)d_in[5];
    const float* wo   = (const float*)d_in[6];
    float* out = (float*)d_out;

    float *q, *k, *v, *attn;
    cudaGetSymbolAddress((void**)&q, g_q);
    cudaGetSymbolAddress((void**)&k, g_k);
    cudaGetSymbolAddress((void**)&v, g_v);
    cudaGetSymbolAddress((void**)&attn, g_attn);

    dim3 gemm_grid(HID / 128, MROWS / 128);   // (8, 64)
    sgemm_nt<<<gemm_grid, 256>>>(x, wq, q, MROWS, HID, HID);
    sgemm_nt<<<gemm_grid, 256>>>(x, wk, k, MROWS, HID, HID);
    sgemm_nt<<<gemm_grid, 256>>>(x, wv, v, MROWS, HID, HID);

    int rope_n = MROWS * NH * 32;
    rope_kernel<<<(rope_n + 255) / 256, 256>>>(q, cosT, sinT);
    rope_kernel<<<(rope_n + 255) / 256, 256>>>(k, cosT, sinT);

    cudaFuncSetAttribute(flash_attn, cudaFuncAttributeMaxDynamicSharedMemorySize,
                         (int)FLASH_SMEM);
    dim3 fgrid(SEQ / 64, BATCH * NH);         // (32, 64)
    flash_attn<<<fgrid, 256, FLASH_SMEM>>>(q, k, v, attn);

    sgemm_nt<<<gemm_grid, 256>>>(attn, wo, out, MROWS, HID, HID);
}

// round 7
// speedup vs baseline: 1.4843x; 1.4260x over previous
#include <cuda_runtime.h>
#include <cuda_bf16.h>
#include <math.h>
#include <stdint.h>

// Problem constants
#define BATCH 4
#define SEQ   2048
#define NH    16
#define HD    64
#define HID   1024           // NH*HD
#define MROWS (BATCH*SEQ)    // 8192

typedef unsigned long long ull;

// ---------------------------------------------------------------------------
// Packed f32x2 helpers
// ---------------------------------------------------------------------------
__device__ __forceinline__ ull pack2(float lo, float hi) {
    ull r;
    asm("mov.b64 %0, {%1, %2};" : "=l"(r) : "f"(lo), "f"(hi));
    return r;
}
__device__ __forceinline__ void unpack2(ull v, float& lo, float& hi) {
    asm("mov.b64 {%0, %1}, %2;" : "=f"(lo), "=f"(hi) : "l"(v));
}
__device__ __forceinline__ void fma2(ull& d, ull a, ull b) {
    asm("fma.rn.f32x2 %0, %1, %2, %3;" : "=l"(d) : "l"(a), "l"(b), "l"(d));
}
__device__ __forceinline__ void mul2(ull& d, ull a, ull b) {
    asm("mul.rn.f32x2 %0, %1, %2;" : "=l"(d) : "l"(a), "l"(b));
}

// ---------------------------------------------------------------------------
// mma.sync m16n8k16 bf16 (arch-portable HMMA; tcgen05 unavailable: harness
// targets family-generic sm_103, not sm_103a)
// ---------------------------------------------------------------------------
#define MMA16816(d, a, b) \
    asm volatile("mma.sync.aligned.m16n8k16.row.col.f32.bf16.bf16.f32 " \
        "{%0,%1,%2,%3}, {%4,%5,%6,%7}, {%8,%9}, {%0,%1,%2,%3};" \
        : "+f"((d)[0]), "+f"((d)[1]), "+f"((d)[2]), "+f"((d)[3]) \
        : "r"((a)[0]), "r"((a)[1]), "r"((a)[2]), "r"((a)[3]), \
          "r"((b)[0]), "r"((b)[1]))

// ---------------------------------------------------------------------------
// Scratch (allocation-free)
// ---------------------------------------------------------------------------
__device__ float g_q[MROWS * HID];
__device__ float g_k[MROWS * HID];
__device__ float g_v[MROWS * HID];
__device__ float g_attn[MROWS * HID];
__device__ __nv_bfloat16 g_xh[MROWS * HID];
__device__ __nv_bfloat16 g_xl[MROWS * HID];
__device__ __nv_bfloat16 g_wh[4 * HID * HID];
__device__ __nv_bfloat16 g_wl[4 * HID * HID];
__device__ __nv_bfloat16 g_ah[MROWS * HID];
__device__ __nv_bfloat16 g_al[MROWS * HID];

// ---------------------------------------------------------------------------
// Split fp32 -> bf16 hi + bf16 lo (residual)
// ---------------------------------------------------------------------------
__global__ void split_kernel(const float* __restrict__ in,
                             __nv_bfloat16* __restrict__ hi,
                             __nv_bfloat16* __restrict__ lo, int n4) {
    int i = blockIdx.x * blockDim.x + threadIdx.x;
    if (i >= n4) return;
    float4 f = reinterpret_cast<const float4*>(in)[i];
    __nv_bfloat16 h0 = __float2bfloat16(f.x);
    __nv_bfloat16 h1 = __float2bfloat16(f.y);
    __nv_bfloat16 h2 = __float2bfloat16(f.z);
    __nv_bfloat16 h3 = __float2bfloat16(f.w);
    __nv_bfloat16 l0 = __float2bfloat16(f.x - __bfloat162float(h0));
    __nv_bfloat16 l1 = __float2bfloat16(f.y - __bfloat162float(h1));
    __nv_bfloat16 l2 = __float2bfloat16(f.z - __bfloat162float(h2));
    __nv_bfloat16 l3 = __float2bfloat16(f.w - __bfloat162float(h3));
    __nv_bfloat162 hp0; hp0.x = h0; hp0.y = h1;
    __nv_bfloat162 hp1; hp1.x = h2; hp1.y = h3;
    __nv_bfloat162 lp0; lp0.x = l0; lp0.y = l1;
    __nv_bfloat162 lp1; lp1.x = l2; lp1.y = l3;
    reinterpret_cast<__nv_bfloat162*>(hi)[i * 2 + 0] = hp0;
    reinterpret_cast<__nv_bfloat162*>(hi)[i * 2 + 1] = hp1;
    reinterpret_cast<__nv_bfloat162*>(lo)[i * 2 + 0] = lp0;
    reinterpret_cast<__nv_bfloat162*>(lo)[i * 2 + 1] = lp1;
}

// ---------------------------------------------------------------------------
// HMMA split-bf16 GEMM: C[m,n] = sum_k A[m,k]*B[n,k]
// A = Ah+Al, B = Bh+Bl (bf16). C = Ah*Bh + Ah*Bl + Al*Bh (fp32 accum).
// Block 128x128, BK=32. 8 warps arranged 4(m) x 2(n); warp tile 32x64.
// Smem stride 40 halves -> conflict-free 32-bit fragment loads.
// ---------------------------------------------------------------------------
#define GK 1024
#define GN 1024
#define LDSB 40

__global__ void __launch_bounds__(256) gemm_mma(
        const __nv_bfloat16* __restrict__ Ah, const __nv_bfloat16* __restrict__ Al,
        const __nv_bfloat16* __restrict__ Bh, const __nv_bfloat16* __restrict__ Bl,
        float* __restrict__ C) {
    __shared__ __nv_bfloat16 sAh[128 * LDSB];
    __shared__ __nv_bfloat16 sAl[128 * LDSB];
    __shared__ __nv_bfloat16 sBh[128 * LDSB];
    __shared__ __nv_bfloat16 sBl[128 * LDSB];

    const int tid  = threadIdx.x;
    const int warp = tid >> 5;
    const int lane = tid & 31;
    const int g    = lane >> 2;   // group (row within frag)
    const int tig  = lane & 3;    // thread in group

    const int m0 = blockIdx.y * 128;
    const int n0 = blockIdx.x * 128;
    const int mbase = (warp & 3) * 32;
    const int nbase = (warp >> 2) * 64;

    const __nv_bfloat16* gA[2] = {Ah + (size_t)m0 * GK, Al + (size_t)m0 * GK};
    const __nv_bfloat16* gB[2] = {Bh + (size_t)n0 * GK, Bl + (size_t)n0 * GK};
    __nv_bfloat16* sA[2] = {sAh, sAl};
    __nv_bfloat16* sB[2] = {sBh, sBl};

    float acc[2][8][4];
#pragma unroll
    for (int mf = 0; mf < 2; mf++)
#pragma unroll
        for (int nf = 0; nf < 8; nf++)
#pragma unroll
            for (int c = 0; c < 4; c++) acc[mf][nf][c] = 0.f;

    for (int k0 = 0; k0 < GK; k0 += 32) {
        // Load 4 tiles: 128 rows x 32 halves each (512 uint4 per tile)
#pragma unroll
        for (int t = 0; t < 2; t++) {
#pragma unroll
            for (int i = 0; i < 2; i++) {
                int s = tid + i * 256;
                int r = s >> 2;
                int c = s & 3;
                *reinterpret_cast<uint4*>(&sA[t][r * LDSB + c * 8]) =
                    *reinterpret_cast<const uint4*>(gA[t] + (size_t)r * GK + k0 + c * 8);
                *reinterpret_cast<uint4*>(&sB[t][r * LDSB + c * 8]) =
                    *reinterpret_cast<const uint4*>(gB[t] + (size_t)r * GK + k0 + c * 8);
            }
        }
        __syncthreads();

#pragma unroll
        for (int kk = 0; kk < 32; kk += 16) {
            uint32_t ah[2][4], al[2][4], bh[8][2], bl[8][2];
#pragma unroll
            for (int mf = 0; mf < 2; mf++) {
                int row = mbase + mf * 16 + g;
                int col = kk + tig * 2;
                ah[mf][0] = *reinterpret_cast<uint32_t*>(&sAh[row * LDSB + col]);
                ah[mf][1] = *reinterpret_cast<uint32_t*>(&sAh[(row + 8) * LDSB + col]);
                ah[mf][2] = *reinterpret_cast<uint32_t*>(&sAh[row * LDSB + col + 8]);
                ah[mf][3] = *reinterpret_cast<uint32_t*>(&sAh[(row + 8) * LDSB + col + 8]);
                al[mf][0] = *reinterpret_cast<uint32_t*>(&sAl[row * LDSB + col]);
                al[mf][1] = *reinterpret_cast<uint32_t*>(&sAl[(row + 8) * LDSB + col]);
                al[mf][2] = *reinterpret_cast<uint32_t*>(&sAl[row * LDSB + col + 8]);
                al[mf][3] = *reinterpret_cast<uint32_t*>(&sAl[(row + 8) * LDSB + col + 8]);
            }
#pragma unroll
            for (int nf = 0; nf < 8; nf++) {
                int row = nbase + nf * 8 + g;
                int col = kk + tig * 2;
                bh[nf][0] = *reinterpret_cast<uint32_t*>(&sBh[row * LDSB + col]);
                bh[nf][1] = *reinterpret_cast<uint32_t*>(&sBh[row * LDSB + col + 8]);
                bl[nf][0] = *reinterpret_cast<uint32_t*>(&sBl[row * LDSB + col]);
                bl[nf][1] = *reinterpret_cast<uint32_t*>(&sBl[row * LDSB + col + 8]);
            }
#pragma unroll
            for (int mf = 0; mf < 2; mf++)
#pragma unroll
                for (int nf = 0; nf < 8; nf++) {
                    MMA16816(acc[mf][nf], ah[mf], bh[nf]);
                    MMA16816(acc[mf][nf], ah[mf], bl[nf]);
                    MMA16816(acc[mf][nf], al[mf], bh[nf]);
                }
        }
        __syncthreads();
    }

    // Epilogue: fp32 stores (float2 per c-pair)
#pragma unroll
    for (int mf = 0; mf < 2; mf++) {
#pragma unroll
        for (int nf = 0; nf < 8; nf++) {
            int row = m0 + mbase + mf * 16 + g;
            int col = n0 + nbase + nf * 8 + tig * 2;
            *reinterpret_cast<float2*>(C + (size_t)row * GN + col) =
                make_float2(acc[mf][nf][0], acc[mf][nf][1]);
            *reinterpret_cast<float2*>(C + (size_t)(row + 8) * GN + col) =
                make_float2(acc[mf][nf][2], acc[mf][nf][3]);
        }
    }
}

// ---------------------------------------------------------------------------
// RoPE (in-place)
// ---------------------------------------------------------------------------
__global__ void rope_kernel(float* __restrict__ qk,
                            const float* __restrict__ cosT,
                            const float* __restrict__ sinT) {
    int idx = blockIdx.x * blockDim.x + threadIdx.x;
    if (idx >= MROWS * NH * 32) return;
    int d = idx & 31;
    int h = (idx >> 5) & (NH - 1);
    int m = idx >> 9;
    int t = m & (SEQ - 1);
    float c = cosT[t * HD + d];
    float s = sinT[t * HD + d];
    size_t base = (size_t)m * HID + h * HD + d;
    float x1 = qk[base];
    float x2 = qk[base + 32];
    qk[base]      = x1 * c - x2 * s;
    qk[base + 32] = x2 * c + x1 * s;
}

// ---------------------------------------------------------------------------
// Flash attention, fp32, causal (f32x2 inner GEMMs, parallel softmax)
// ---------------------------------------------------------------------------
#define FLASH_SMEM ((3 * 64 * 64 + 64 * 65 + 3 * 64) * sizeof(float))

__global__ void __launch_bounds__(256) flash_attn(const float* __restrict__ q,
                                                  const float* __restrict__ k,
                                                  const float* __restrict__ v,
                                                  float* __restrict__ o) {
    extern __shared__ float sm[];
    float* Qt   = sm;
    float* Kt   = Qt + 64 * 64;
    float* Vs   = Kt + 64 * 64;
    float* Ps   = Vs + 64 * 64;
    float* mrow = Ps + 64 * 65;
    float* lrow = mrow + 64;
    float* crow = lrow + 64;

    const int qt = blockIdx.x;
    const int bh = blockIdx.y;
    const int b = bh >> 4;
    const int h = bh & 15;
    const int tid = threadIdx.x;
    const int tx = tid & 15;
    const int ty = tid >> 4;

    const size_t baseQ  = ((size_t)b * SEQ + qt * 64) * HID + h * HD;
    const size_t baseKV = (size_t)b * SEQ * HID + h * HD;

    for (int e = tid; e < 64 * 16; e += 256) {
        int r = e >> 4;
        int c = (e & 15) * 4;
        float4 val = *reinterpret_cast<const float4*>(q + baseQ + (size_t)r * HID + c);
        Qt[(c + 0) * 64 + r] = val.x; Qt[(c + 1) * 64 + r] = val.y;
        Qt[(c + 2) * 64 + r] = val.z; Qt[(c + 3) * 64 + r] = val.w;
    }
    if (tid < 64) { mrow[tid] = -INFINITY; lrow[tid] = 0.f; }

    ull accO2[4][2];
    const ull zz = pack2(0.f, 0.f);
#pragma unroll
    for (int i = 0; i < 4; i++) { accO2[i][0] = zz; accO2[i][1] = zz; }

    __syncthreads();

    for (int jt = 0; jt <= qt; jt++) {
        const float* kb = k + baseKV + (size_t)jt * 64 * HID;
        const float* vb = v + baseKV + (size_t)jt * 64 * HID;
        for (int e = tid; e < 64 * 16; e += 256) {
            int r = e >> 4;
            int c = (e & 15) * 4;
            float4 kv = *reinterpret_cast<const float4*>(kb + (size_t)r * HID + c);
            Kt[(c + 0) * 64 + r] = kv.x; Kt[(c + 1) * 64 + r] = kv.y;
            Kt[(c + 2) * 64 + r] = kv.z; Kt[(c + 3) * 64 + r] = kv.w;
            *reinterpret_cast<float4*>(&Vs[r * 64 + c]) =
                *reinterpret_cast<const float4*>(vb + (size_t)r * HID + c);
        }
        __syncthreads();

        ull accS2[4][2];
#pragma unroll
        for (int i = 0; i < 4; i++) { accS2[i][0] = zz; accS2[i][1] = zz; }

#pragma unroll 8
        for (int d = 0; d < 64; d++) {
            float4 af = *reinterpret_cast<float4*>(&Qt[d * 64 + ty * 4]);
            float4 bf = *reinterpret_cast<float4*>(&Kt[d * 64 + tx * 4]);
            ull b2[2];
            b2[0] = *reinterpret_cast<ull*>(&bf.x);
            b2[1] = *reinterpret_cast<ull*>(&bf.z);
            float ar[4] = {af.x, af.y, af.z, af.w};
#pragma unroll
            for (int i = 0; i < 4; i++) {
                ull a2 = pack2(ar[i], ar[i]);
                fma2(accS2[i][0], a2, b2[0]);
                fma2(accS2[i][1], a2, b2[1]);
            }
        }

        const float scale = 0.125f;
        const bool diag = (jt == qt);
#pragma unroll
        for (int i = 0; i < 4; i++) {
            float s0, s1, s2, s3;
            unpack2(accS2[i][0], s0, s1);
            unpack2(accS2[i][1], s2, s3);
            float sv[4] = {s0, s1, s2, s3};
#pragma unroll
            for (int j = 0; j < 4; j++) {
                float s = sv[j] * scale;
                if (diag && (tx * 4 + j) > (ty * 4 + i)) s = -INFINITY;
                Ps[(ty * 4 + i) * 65 + tx * 4 + j] = s;
            }
        }
        __syncthreads();

        {
            int r  = tid >> 2;
            int qd = tid & 3;
            float* pr = &Ps[r * 65 + qd * 16];
            float mo = mrow[r];
            float m4 = -INFINITY;
#pragma unroll
            for (int c = 0; c < 16; c++) m4 = fmaxf(m4, pr[c]);
            m4 = fmaxf(m4, __shfl_xor_sync(0xFFFFFFFF, m4, 1));
            m4 = fmaxf(m4, __shfl_xor_sync(0xFFFFFFFF, m4, 2));
            float mn = fmaxf(mo, m4);
            float sum = 0.f;
#pragma unroll
            for (int c = 0; c < 16; c++) {
                float p = __expf(pr[c] - mn);
                pr[c] = p;
                sum += p;
            }
            sum += __shfl_xor_sync(0xFFFFFFFF, sum, 1);
            sum += __shfl_xor_sync(0xFFFFFFFF, sum, 2);
            if (qd == 0) {
                float corr = __expf(mo - mn);
                mrow[r] = mn;
                lrow[r] = lrow[r] * corr + sum;
                crow[r] = corr;
            }
        }
        __syncthreads();

#pragma unroll
        for (int i = 0; i < 4; i++) {
            ull c2 = pack2(crow[ty * 4 + i], crow[ty * 4 + i]);
            mul2(accO2[i][0], accO2[i][0], c2);
            mul2(accO2[i][1], accO2[i][1], c2);
        }

#pragma unroll 8
        for (int kk = 0; kk < 64; kk++) {
            float4 bf = *reinterpret_cast<float4*>(&Vs[kk * 64 + tx * 4]);
            ull b2[2];
            b2[0] = *reinterpret_cast<ull*>(&bf.x);
            b2[1] = *reinterpret_cast<ull*>(&bf.z);
#pragma unroll
            for (int i = 0; i < 4; i++) {
                ull a2 = pack2(Ps[(ty * 4 + i) * 65 + kk], Ps[(ty * 4 + i) * 65 + kk]);
                fma2(accO2[i][0], a2, b2[0]);
                fma2(accO2[i][1], a2, b2[1]);
            }
        }
        __syncthreads();
    }

#pragma unroll
    for (int i = 0; i < 4; i++) {
        int qrow = qt * 64 + ty * 4 + i;
        float inv = 1.f / lrow[ty * 4 + i];
        float o0, o1, o2, o3;
        unpack2(accO2[i][0], o0, o1);
        unpack2(accO2[i][1], o2, o3);
        float4 val = make_float4(o0 * inv, o1 * inv, o2 * inv, o3 * inv);
        *reinterpret_cast<float4*>(o + ((size_t)b * SEQ + qrow) * HID + h * HD + tx * 4) = val;
    }
}

// ---------------------------------------------------------------------------
// Launch
// ---------------------------------------------------------------------------
extern "C" void kernel_launch(void* const* d_in, const int* in_sizes, int n_in,
                              void* d_out, int out_size) {
    const float* x    = (const float*)d_in[0];
    const float* cosT = (const float*)d_in[1];
    const float* sinT = (const float*)d_in[2];
    const float* wq   = (const float*)d_in[3];
    const float* wk   = (const float*)d_in[4];
    const float* wv   = (const float*)d_in[5];
    const float* wo   = (const float*)d_in[6];
    float* out = (float*)d_out;

    float *q, *k, *v, *attn;
    __nv_bfloat16 *xh, *xl, *wh, *wl, *ah, *al;
    cudaGetSymbolAddress((void**)&q, g_q);
    cudaGetSymbolAddress((void**)&k, g_k);
    cudaGetSymbolAddress((void**)&v, g_v);
    cudaGetSymbolAddress((void**)&attn, g_attn);
    cudaGetSymbolAddress((void**)&xh, g_xh);
    cudaGetSymbolAddress((void**)&xl, g_xl);
    cudaGetSymbolAddress((void**)&wh, g_wh);
    cudaGetSymbolAddress((void**)&wl, g_wl);
    cudaGetSymbolAddress((void**)&ah, g_ah);
    cudaGetSymbolAddress((void**)&al, g_al);

    cudaFuncSetAttribute(flash_attn, cudaFuncAttributeMaxDynamicSharedMemorySize,
                         (int)FLASH_SMEM);

    // Split inputs to bf16 hi/lo
    int x4 = MROWS * HID / 4;
    int w4 = HID * HID / 4;
    split_kernel<<<(x4 + 255) / 256, 256>>>(x, xh, xl, x4);
    split_kernel<<<(w4 + 255) / 256, 256>>>(wq, wh + 0 * HID * HID, wl + 0 * HID * HID, w4);
    split_kernel<<<(w4 + 255) / 256, 256>>>(wk, wh + 1 * HID * HID, wl + 1 * HID * HID, w4);
    split_kernel<<<(w4 + 255) / 256, 256>>>(wv, wh + 2 * HID * HID, wl + 2 * HID * HID, w4);
    split_kernel<<<(w4 + 255) / 256, 256>>>(wo, wh + 3 * HID * HID, wl + 3 * HID * HID, w4);

    dim3 ggrid(HID / 128, MROWS / 128);   // (8, 64)
    gemm_mma<<<ggrid, 256>>>(xh, xl, wh + 0 * HID * HID, wl + 0 * HID * HID, q);
    gemm_mma<<<ggrid, 256>>>(xh, xl, wh + 1 * HID * HID, wl + 1 * HID * HID, k);
    gemm_mma<<<ggrid, 256>>>(xh, xl, wh + 2 * HID * HID, wl + 2 * HID * HID, v);

    int rope_n = MROWS * NH * 32;
    rope_kernel<<<(rope_n + 255) / 256, 256>>>(q, cosT, sinT);
    rope_kernel<<<(rope_n + 255) / 256, 256>>>(k, cosT, sinT);

    dim3 fgrid(SEQ / 64, BATCH * NH);     // (32, 64)
    flash_attn<<<fgrid, 256, FLASH_SMEM>>>(q, k, v, attn);

    split_kernel<<<(x4 + 255) / 256, 256>>>(attn, ah, al, x4);
    gemm_mma<<<ggrid, 256>>>(ah, al, wh + 3 * HID * HID, wl + 3 * HID * HID, out);
}

// round 9
// speedup vs baseline: 2.1422x; 1.4433x over previous
#include <cuda_runtime.h>
#include <cuda_bf16.h>
#include <math.h>
#include <stdint.h>

// Problem constants
#define BATCH 4
#define SEQ   2048
#define NH    16
#define HD    64
#define HID   1024           // NH*HD
#define MROWS (BATCH*SEQ)    // 8192

// ---------------------------------------------------------------------------
// mma.sync m16n8k16 bf16 (arch-portable HMMA; tcgen05 unavailable: harness
// targets family-generic sm_103, not sm_103a)
// ---------------------------------------------------------------------------
#define MMA16816(d, a, b) \
    asm volatile("mma.sync.aligned.m16n8k16.row.col.f32.bf16.bf16.f32 " \
        "{%0,%1,%2,%3}, {%4,%5,%6,%7}, {%8,%9}, {%0,%1,%2,%3};" \
        : "+f"((d)[0]), "+f"((d)[1]), "+f"((d)[2]), "+f"((d)[3]) \
        : "r"((a)[0]), "r"((a)[1]), "r"((a)[2]), "r"((a)[3]), \
          "r"((b)[0]), "r"((b)[1]))

// Split two fp32 into packed bf16 hi-pair and lo-pair (residual)
__device__ __forceinline__ void split_pack(float x, float y,
                                           uint32_t& hp, uint32_t& lp) {
    __nv_bfloat16 hx = __float2bfloat16(x);
    __nv_bfloat16 hy = __float2bfloat16(y);
    __nv_bfloat16 lx = __float2bfloat16(x - __bfloat162float(hx));
    __nv_bfloat16 ly = __float2bfloat16(y - __bfloat162float(hy));
    __nv_bfloat162 H; H.x = hx; H.y = hy;
    __nv_bfloat162 L; L.x = lx; L.y = ly;
    hp = *reinterpret_cast<uint32_t*>(&H);
    lp = *reinterpret_cast<uint32_t*>(&L);
}

// ---------------------------------------------------------------------------
// Scratch (allocation-free)
// ---------------------------------------------------------------------------
__device__ float g_q[MROWS * HID];
__device__ float g_k[MROWS * HID];
__device__ float g_v[MROWS * HID];
__device__ float g_attn[MROWS * HID];
__device__ __nv_bfloat16 g_xh[MROWS * HID];
__device__ __nv_bfloat16 g_xl[MROWS * HID];
__device__ __nv_bfloat16 g_wh[4 * HID * HID];
__device__ __nv_bfloat16 g_wl[4 * HID * HID];
__device__ __nv_bfloat16 g_ah[MROWS * HID];
__device__ __nv_bfloat16 g_al[MROWS * HID];
__device__ __nv_bfloat16 g_qh[MROWS * HID];
__device__ __nv_bfloat16 g_ql[MROWS * HID];
__device__ __nv_bfloat16 g_kh[MROWS * HID];
__device__ __nv_bfloat16 g_kl[MROWS * HID];
__device__ __nv_bfloat16 g_vh[MROWS * HID];
__device__ __nv_bfloat16 g_vl[MROWS * HID];

// ---------------------------------------------------------------------------
// Split fp32 -> bf16 hi + bf16 lo (residual)
// ---------------------------------------------------------------------------
__global__ void split_kernel(const float* __restrict__ in,
                             __nv_bfloat16* __restrict__ hi,
                             __nv_bfloat16* __restrict__ lo, int n4) {
    int i = blockIdx.x * blockDim.x + threadIdx.x;
    if (i >= n4) return;
    float4 f = reinterpret_cast<const float4*>(in)[i];
    __nv_bfloat16 h0 = __float2bfloat16(f.x);
    __nv_bfloat16 h1 = __float2bfloat16(f.y);
    __nv_bfloat16 h2 = __float2bfloat16(f.z);
    __nv_bfloat16 h3 = __float2bfloat16(f.w);
    __nv_bfloat16 l0 = __float2bfloat16(f.x - __bfloat162float(h0));
    __nv_bfloat16 l1 = __float2bfloat16(f.y - __bfloat162float(h1));
    __nv_bfloat16 l2 = __float2bfloat16(f.z - __bfloat162float(h2));
    __nv_bfloat16 l3 = __float2bfloat16(f.w - __bfloat162float(h3));
    __nv_bfloat162 hp0; hp0.x = h0; hp0.y = h1;
    __nv_bfloat162 hp1; hp1.x = h2; hp1.y = h3;
    __nv_bfloat162 lp0; lp0.x = l0; lp0.y = l1;
    __nv_bfloat162 lp1; lp1.x = l2; lp1.y = l3;
    reinterpret_cast<__nv_bfloat162*>(hi)[i * 2 + 0] = hp0;
    reinterpret_cast<__nv_bfloat162*>(hi)[i * 2 + 1] = hp1;
    reinterpret_cast<__nv_bfloat162*>(lo)[i * 2 + 0] = lp0;
    reinterpret_cast<__nv_bfloat162*>(lo)[i * 2 + 1] = lp1;
}

// ---------------------------------------------------------------------------
// RoPE + optional scale + bf16 hi/lo split (reads fp32, writes bf16 pair)
// ---------------------------------------------------------------------------
__global__ void rope_split(const float* __restrict__ src,
                           __nv_bfloat16* __restrict__ hi,
                           __nv_bfloat16* __restrict__ lo,
                           const float* __restrict__ cosT,
                           const float* __restrict__ sinT, float scale) {
    int idx = blockIdx.x * blockDim.x + threadIdx.x;
    if (idx >= MROWS * NH * 32) return;
    int d = idx & 31;
    int h = (idx >> 5) & (NH - 1);
    int m = idx >> 9;
    int t = m & (SEQ - 1);
    float c = cosT[t * HD + d];
    float s = sinT[t * HD + d];
    size_t base = (size_t)m * HID + h * HD + d;
    float x1 = src[base];
    float x2 = src[base + 32];
    float r1 = (x1 * c - x2 * s) * scale;
    float r2 = (x2 * c + x1 * s) * scale;
    __nv_bfloat16 h1 = __float2bfloat16(r1);
    __nv_bfloat16 h2 = __float2bfloat16(r2);
    hi[base]      = h1;
    hi[base + 32] = h2;
    lo[base]      = __float2bfloat16(r1 - __bfloat162float(h1));
    lo[base + 32] = __float2bfloat16(r2 - __bfloat162float(h2));
}

// ---------------------------------------------------------------------------
// HMMA split-bf16 GEMM: C[m,n] = sum_k A[m,k]*B[n,k]
// Block 128x128, BK=32. 8 warps 4(m)x2(n); warp tile 32x64.
// ---------------------------------------------------------------------------
#define GK 1024
#define GN 1024
#define LDSB 40

__global__ void __launch_bounds__(256) gemm_mma(
        const __nv_bfloat16* __restrict__ Ah, const __nv_bfloat16* __restrict__ Al,
        const __nv_bfloat16* __restrict__ Bh, const __nv_bfloat16* __restrict__ Bl,
        float* __restrict__ C) {
    __shared__ __nv_bfloat16 sAh[128 * LDSB];
    __shared__ __nv_bfloat16 sAl[128 * LDSB];
    __shared__ __nv_bfloat16 sBh[128 * LDSB];
    __shared__ __nv_bfloat16 sBl[128 * LDSB];

    const int tid  = threadIdx.x;
    const int warp = tid >> 5;
    const int lane = tid & 31;
    const int g    = lane >> 2;
    const int tig  = lane & 3;

    const int m0 = blockIdx.y * 128;
    const int n0 = blockIdx.x * 128;
    const int mbase = (warp & 3) * 32;
    const int nbase = (warp >> 2) * 64;

    const __nv_bfloat16* gA[2] = {Ah + (size_t)m0 * GK, Al + (size_t)m0 * GK};
    const __nv_bfloat16* gB[2] = {Bh + (size_t)n0 * GK, Bl + (size_t)n0 * GK};
    __nv_bfloat16* sA[2] = {sAh, sAl};
    __nv_bfloat16* sB[2] = {sBh, sBl};

    float acc[2][8][4];
#pragma unroll
    for (int mf = 0; mf < 2; mf++)
#pragma unroll
        for (int nf = 0; nf < 8; nf++)
#pragma unroll
            for (int c = 0; c < 4; c++) acc[mf][nf][c] = 0.f;

    for (int k0 = 0; k0 < GK; k0 += 32) {
#pragma unroll
        for (int t = 0; t < 2; t++) {
#pragma unroll
            for (int i = 0; i < 2; i++) {
                int s = tid + i * 256;
                int r = s >> 2;
                int c = s & 3;
                *reinterpret_cast<uint4*>(&sA[t][r * LDSB + c * 8]) =
                    *reinterpret_cast<const uint4*>(gA[t] + (size_t)r * GK + k0 + c * 8);
                *reinterpret_cast<uint4*>(&sB[t][r * LDSB + c * 8]) =
                    *reinterpret_cast<const uint4*>(gB[t] + (size_t)r * GK + k0 + c * 8);
            }
        }
        __syncthreads();

#pragma unroll
        for (int kk = 0; kk < 32; kk += 16) {
            uint32_t ah[2][4], al[2][4], bh[8][2], bl[8][2];
#pragma unroll
            for (int mf = 0; mf < 2; mf++) {
                int row = mbase + mf * 16 + g;
                int col = kk + tig * 2;
                ah[mf][0] = *reinterpret_cast<uint32_t*>(&sAh[row * LDSB + col]);
                ah[mf][1] = *reinterpret_cast<uint32_t*>(&sAh[(row + 8) * LDSB + col]);
                ah[mf][2] = *reinterpret_cast<uint32_t*>(&sAh[row * LDSB + col + 8]);
                ah[mf][3] = *reinterpret_cast<uint32_t*>(&sAh[(row + 8) * LDSB + col + 8]);
                al[mf][0] = *reinterpret_cast<uint32_t*>(&sAl[row * LDSB + col]);
                al[mf][1] = *reinterpret_cast<uint32_t*>(&sAl[(row + 8) * LDSB + col]);
                al[mf][2] = *reinterpret_cast<uint32_t*>(&sAl[row * LDSB + col + 8]);
                al[mf][3] = *reinterpret_cast<uint32_t*>(&sAl[(row + 8) * LDSB + col + 8]);
            }
#pragma unroll
            for (int nf = 0; nf < 8; nf++) {
                int row = nbase + nf * 8 + g;
                int col = kk + tig * 2;
                bh[nf][0] = *reinterpret_cast<uint32_t*>(&sBh[row * LDSB + col]);
                bh[nf][1] = *reinterpret_cast<uint32_t*>(&sBh[row * LDSB + col + 8]);
                bl[nf][0] = *reinterpret_cast<uint32_t*>(&sBl[row * LDSB + col]);
                bl[nf][1] = *reinterpret_cast<uint32_t*>(&sBl[row * LDSB + col + 8]);
            }
#pragma unroll
            for (int mf = 0; mf < 2; mf++)
#pragma unroll
                for (int nf = 0; nf < 8; nf++) {
                    MMA16816(acc[mf][nf], ah[mf], bh[nf]);
                    MMA16816(acc[mf][nf], ah[mf], bl[nf]);
                    MMA16816(acc[mf][nf], al[mf], bh[nf]);
                }
        }
        __syncthreads();
    }

#pragma unroll
    for (int mf = 0; mf < 2; mf++) {
#pragma unroll
        for (int nf = 0; nf < 8; nf++) {
            int row = m0 + mbase + mf * 16 + g;
            int col = n0 + nbase + nf * 8 + tig * 2;
            *reinterpret_cast<float2*>(C + (size_t)row * GN + col) =
                make_float2(acc[mf][nf][0], acc[mf][nf][1]);
            *reinterpret_cast<float2*>(C + (size_t)(row + 8) * GN + col) =
                make_float2(acc[mf][nf][2], acc[mf][nf][3]);
        }
    }
}

// ---------------------------------------------------------------------------
// HMMA flash attention (FA2-style): 4 warps, 64-query tile, causal.
// Q pre-scaled by 1/sqrt(D) and split to bf16 hi/lo (rope_split).
// QK^T and P*V both 3-pass split-bf16. Softmax fully in registers.
// ---------------------------------------------------------------------------
#define AT_STR 72   // smem row stride in halves (conflict-free frag loads)

__global__ void __launch_bounds__(128) flash_mma(
        const __nv_bfloat16* __restrict__ qh, const __nv_bfloat16* __restrict__ ql,
        const __nv_bfloat16* __restrict__ kh, const __nv_bfloat16* __restrict__ kl,
        const __nv_bfloat16* __restrict__ vh, const __nv_bfloat16* __restrict__ vl,
        float* __restrict__ o) {
    __shared__ __nv_bfloat16 sA[64 * AT_STR];   // Qh, then Vh^T per tile
    __shared__ __nv_bfloat16 sB[64 * AT_STR];   // Ql, then Vl^T per tile
    __shared__ __nv_bfloat16 sKh[64 * AT_STR];
    __shared__ __nv_bfloat16 sKl[64 * AT_STR];

    const int qt = blockIdx.x;
    const int bh = blockIdx.y;
    const int b = bh >> 4;
    const int h = bh & 15;
    const int tid = threadIdx.x;
    const int w = tid >> 5;
    const int lane = tid & 31;
    const int g = lane >> 2;
    const int tig = lane & 3;

    const size_t baseQ  = ((size_t)b * SEQ + qt * 64) * HID + h * HD;
    const size_t baseKV = (size_t)b * SEQ * HID + h * HD;

    // Stage Q tile (row-major: q-row x d) into sA/sB
    for (int s = tid; s < 512; s += 128) {
        int r = s >> 3;
        int c8 = (s & 7) * 8;
        *reinterpret_cast<uint4*>(&sA[r * AT_STR + c8]) =
            *reinterpret_cast<const uint4*>(qh + baseQ + (size_t)r * HID + c8);
        *reinterpret_cast<uint4*>(&sB[r * AT_STR + c8]) =
            *reinterpret_cast<const uint4*>(ql + baseQ + (size_t)r * HID + c8);
    }
    __syncthreads();

    // Extract persistent Q A-fragments (4 k16 chunks, hi+lo)
    uint32_t qfh[4][4], qfl[4][4];
    {
        int row = w * 16 + g;
#pragma unroll
        for (int kc = 0; kc < 4; kc++) {
            int c = kc * 16 + tig * 2;
            qfh[kc][0] = *reinterpret_cast<uint32_t*>(&sA[row * AT_STR + c]);
            qfh[kc][1] = *reinterpret_cast<uint32_t*>(&sA[(row + 8) * AT_STR + c]);
            qfh[kc][2] = *reinterpret_cast<uint32_t*>(&sA[row * AT_STR + c + 8]);
            qfh[kc][3] = *reinterpret_cast<uint32_t*>(&sA[(row + 8) * AT_STR + c + 8]);
            qfl[kc][0] = *reinterpret_cast<uint32_t*>(&sB[row * AT_STR + c]);
            qfl[kc][1] = *reinterpret_cast<uint32_t*>(&sB[(row + 8) * AT_STR + c]);
            qfl[kc][2] = *reinterpret_cast<uint32_t*>(&sB[row * AT_STR + c + 8]);
            qfl[kc][3] = *reinterpret_cast<uint32_t*>(&sB[(row + 8) * AT_STR + c + 8]);
        }
    }
    __syncthreads();

    float O[8][4];
#pragma unroll
    for (int nf = 0; nf < 8; nf++)
#pragma unroll
        for (int c = 0; c < 4; c++) O[nf][c] = 0.f;
    float m0 = -INFINITY, m1 = -INFINITY, l0 = 0.f, l1 = 0.f;

    for (int jt = 0; jt <= qt; jt++) {
        const __nv_bfloat16* kbh = kh + baseKV + (size_t)jt * 64 * HID;
        const __nv_bfloat16* kbl = kl + baseKV + (size_t)jt * 64 * HID;
        const __nv_bfloat16* vbh = vh + baseKV + (size_t)jt * 64 * HID;
        const __nv_bfloat16* vbl = vl + baseKV + (size_t)jt * 64 * HID;

        // K tiles (row-major key x d)
        for (int s = tid; s < 512; s += 128) {
            int r = s >> 3;
            int c8 = (s & 7) * 8;
            *reinterpret_cast<uint4*>(&sKh[r * AT_STR + c8]) =
                *reinterpret_cast<const uint4*>(kbh + (size_t)r * HID + c8);
            *reinterpret_cast<uint4*>(&sKl[r * AT_STR + c8]) =
                *reinterpret_cast<const uint4*>(kbl + (size_t)r * HID + c8);
        }
        // V tiles transposed into sA/sB: sV[d][key]
        for (int s = tid; s < 512; s += 128) {
            int kk = s & 63;
            int d8 = (s >> 6) * 8;
            uint4 hv = *reinterpret_cast<const uint4*>(vbh + (size_t)kk * HID + d8);
            uint4 lv = *reinterpret_cast<const uint4*>(vbl + (size_t)kk * HID + d8);
            const __nv_bfloat16* hp = reinterpret_cast<const __nv_bfloat16*>(&hv);
            const __nv_bfloat16* lp = reinterpret_cast<const __nv_bfloat16*>(&lv);
#pragma unroll
            for (int j = 0; j < 8; j++) {
                sA[(d8 + j) * AT_STR + kk] = hp[j];
                sB[(d8 + j) * AT_STR + kk] = lp[j];
            }
        }
        __syncthreads();

        // S = Q K^T (16x64 per warp), 3-pass split
        float S[8][4];
#pragma unroll
        for (int nf = 0; nf < 8; nf++)
#pragma unroll
            for (int c = 0; c < 4; c++) S[nf][c] = 0.f;

#pragma unroll
        for (int nf = 0; nf < 8; nf++) {
            int rowb = nf * 8 + g;
#pragma unroll
            for (int kc = 0; kc < 4; kc++) {
                int c = kc * 16 + tig * 2;
                uint32_t bkh[2], bkl[2];
                bkh[0] = *reinterpret_cast<uint32_t*>(&sKh[rowb * AT_STR + c]);
                bkh[1] = *reinterpret_cast<uint32_t*>(&sKh[rowb * AT_STR + c + 8]);
                bkl[0] = *reinterpret_cast<uint32_t*>(&sKl[rowb * AT_STR + c]);
                bkl[1] = *reinterpret_cast<uint32_t*>(&sKl[rowb * AT_STR + c + 8]);
                MMA16816(S[nf], qfh[kc], bkh);
                MMA16816(S[nf], qfh[kc], bkl);
                MMA16816(S[nf], qfl[kc], bkh);
            }
        }

        // Causal mask (diagonal tile only)
        if (jt == qt) {
            int lr0 = w * 16 + g;
            int lr1 = lr0 + 8;
#pragma unroll
            for (int nf = 0; nf < 8; nf++) {
                int jc = nf * 8 + tig * 2;
                if (jc > lr0)     S[nf][0] = -INFINITY;
                if (jc + 1 > lr0) S[nf][1] = -INFINITY;
                if (jc > lr1)     S[nf][2] = -INFINITY;
                if (jc + 1 > lr1) S[nf][3] = -INFINITY;
            }
        }

        // Online softmax in registers (quad = 4 threads share a row)
        float mx0 = -INFINITY, mx1 = -INFINITY;
#pragma unroll
        for (int nf = 0; nf < 8; nf++) {
            mx0 = fmaxf(mx0, fmaxf(S[nf][0], S[nf][1]));
            mx1 = fmaxf(mx1, fmaxf(S[nf][2], S[nf][3]));
        }
        mx0 = fmaxf(mx0, __shfl_xor_sync(0xFFFFFFFF, mx0, 1));
        mx0 = fmaxf(mx0, __shfl_xor_sync(0xFFFFFFFF, mx0, 2));
        mx1 = fmaxf(mx1, __shfl_xor_sync(0xFFFFFFFF, mx1, 1));
        mx1 = fmaxf(mx1, __shfl_xor_sync(0xFFFFFFFF, mx1, 2));
        float nm0 = fmaxf(m0, mx0);
        float nm1 = fmaxf(m1, mx1);
        float corr0 = __expf(m0 - nm0);
        float corr1 = __expf(m1 - nm1);
        m0 = nm0; m1 = nm1;
        float sum0 = 0.f, sum1 = 0.f;
#pragma unroll
        for (int nf = 0; nf < 8; nf++) {
            S[nf][0] = __expf(S[nf][0] - m0); sum0 += S[nf][0];
            S[nf][1] = __expf(S[nf][1] - m0); sum0 += S[nf][1];
            S[nf][2] = __expf(S[nf][2] - m1); sum1 += S[nf][2];
            S[nf][3] = __expf(S[nf][3] - m1); sum1 += S[nf][3];
        }
        sum0 += __shfl_xor_sync(0xFFFFFFFF, sum0, 1);
        sum0 += __shfl_xor_sync(0xFFFFFFFF, sum0, 2);
        sum1 += __shfl_xor_sync(0xFFFFFFFF, sum1, 1);
        sum1 += __shfl_xor_sync(0xFFFFFFFF, sum1, 2);
        l0 = l0 * corr0 + sum0;
        l1 = l1 * corr1 + sum1;
#pragma unroll
        for (int nf = 0; nf < 8; nf++) {
            O[nf][0] *= corr0; O[nf][1] *= corr0;
            O[nf][2] *= corr1; O[nf][3] *= corr1;
        }

        // Re-pack S (C-frag) directly into P A-frags (hi/lo), no smem trip
        uint32_t aPh[4][4], aPl[4][4];
#pragma unroll
        for (int kc = 0; kc < 4; kc++) {
            split_pack(S[2 * kc][0],     S[2 * kc][1],     aPh[kc][0], aPl[kc][0]);
            split_pack(S[2 * kc][2],     S[2 * kc][3],     aPh[kc][1], aPl[kc][1]);
            split_pack(S[2 * kc + 1][0], S[2 * kc + 1][1], aPh[kc][2], aPl[kc][2]);
            split_pack(S[2 * kc + 1][2], S[2 * kc + 1][3], aPh[kc][3], aPl[kc][3]);
        }

        // O += P @ V (V^T in sA/sB), 3-pass split
#pragma unroll
        for (int nf = 0; nf < 8; nf++) {
            int rowb = nf * 8 + g;
#pragma unroll
            for (int kc = 0; kc < 4; kc++) {
                int c = kc * 16 + tig * 2;
                uint32_t bvh[2], bvl[2];
                bvh[0] = *reinterpret_cast<uint32_t*>(&sA[rowb * AT_STR + c]);
                bvh[1] = *reinterpret_cast<uint32_t*>(&sA[rowb * AT_STR + c + 8]);
                bvl[0] = *reinterpret_cast<uint32_t*>(&sB[rowb * AT_STR + c]);
                bvl[1] = *reinterpret_cast<uint32_t*>(&sB[rowb * AT_STR + c + 8]);
                MMA16816(O[nf], aPh[kc], bvh);
                MMA16816(O[nf], aPh[kc], bvl);
                MMA16816(O[nf], aPl[kc], bvh);
            }
        }
        __syncthreads();
    }

    // Normalize + write
    float inv0 = 1.f / l0;
    float inv1 = 1.f / l1;
    int row0 = qt * 64 + w * 16 + g;
#pragma unroll
    for (int nf = 0; nf < 8; nf++) {
        int col = nf * 8 + tig * 2;
        *reinterpret_cast<float2*>(o + ((size_t)b * SEQ + row0) * HID + h * HD + col) =
            make_float2(O[nf][0] * inv0, O[nf][1] * inv0);
        *reinterpret_cast<float2*>(o + ((size_t)b * SEQ + row0 + 8) * HID + h * HD + col) =
            make_float2(O[nf][2] * inv1, O[nf][3] * inv1);
    }
}

// ---------------------------------------------------------------------------
// Launch
// ---------------------------------------------------------------------------
extern "C" void kernel_launch(void* const* d_in, const int* in_sizes, int n_in,
                              void* d_out, int out_size) {
    const float* x    = (const float*)d_in[0];
    const float* cosT = (const float*)d_in[1];
    const float* sinT = (const float*)d_in[2];
    const float* wq   = (const float*)d_in[3];
    const float* wk   = (const float*)d_in[4];
    const float* wv   = (const float*)d_in[5];
    const float* wo   = (const float*)d_in[6];
    float* out = (float*)d_out;

    float *q, *k, *v, *attn;
    __nv_bfloat16 *xh, *xl, *wh, *wl, *ah, *al;
    __nv_bfloat16 *qhp, *qlp, *khp, *klp, *vhp, *vlp;
    cudaGetSymbolAddress((void**)&q, g_q);
    cudaGetSymbolAddress((void**)&k, g_k);
    cudaGetSymbolAddress((void**)&v, g_v);
    cudaGetSymbolAddress((void**)&attn, g_attn);
    cudaGetSymbolAddress((void**)&xh, g_xh);
    cudaGetSymbolAddress((void**)&xl, g_xl);
    cudaGetSymbolAddress((void**)&wh, g_wh);
    cudaGetSymbolAddress((void**)&wl, g_wl);
    cudaGetSymbolAddress((void**)&ah, g_ah);
    cudaGetSymbolAddress((void**)&al, g_al);
    cudaGetSymbolAddress((void**)&qhp, g_qh);
    cudaGetSymbolAddress((void**)&qlp, g_ql);
    cudaGetSymbolAddress((void**)&khp, g_kh);
    cudaGetSymbolAddress((void**)&klp, g_kl);
    cudaGetSymbolAddress((void**)&vhp, g_vh);
    cudaGetSymbolAddress((void**)&vlp, g_vl);

    // Split inputs to bf16 hi/lo
    int x4 = MROWS * HID / 4;
    int w4 = HID * HID / 4;
    split_kernel<<<(x4 + 255) / 256, 256>>>(x, xh, xl, x4);
    split_kernel<<<(w4 + 255) / 256, 256>>>(wq, wh + 0 * HID * HID, wl + 0 * HID * HID, w4);
    split_kernel<<<(w4 + 255) / 256, 256>>>(wk, wh + 1 * HID * HID, wl + 1 * HID * HID, w4);
    split_kernel<<<(w4 + 255) / 256, 256>>>(wv, wh + 2 * HID * HID, wl + 2 * HID * HID, w4);
    split_kernel<<<(w4 + 255) / 256, 256>>>(wo, wh + 3 * HID * HID, wl + 3 * HID * HID, w4);

    dim3 ggrid(HID / 128, MROWS / 128);   // (8, 64)
    gemm_mma<<<ggrid, 256>>>(xh, xl, wh + 0 * HID * HID, wl + 0 * HID * HID, q);
    gemm_mma<<<ggrid, 256>>>(xh, xl, wh + 1 * HID * HID, wl + 1 * HID * HID, k);
    gemm_mma<<<ggrid, 256>>>(xh, xl, wh + 2 * HID * HID, wl + 2 * HID * HID, v);

    // RoPE + scale(Q only) + bf16 split; V plain split
    int rope_n = MROWS * NH * 32;
    rope_split<<<(rope_n + 255) / 256, 256>>>(q, qhp, qlp, cosT, sinT, 0.125f);
    rope_split<<<(rope_n + 255) / 256, 256>>>(k, khp, klp, cosT, sinT, 1.0f);
    split_kernel<<<(x4 + 255) / 256, 256>>>(v, vhp, vlp, x4);

    dim3 fgrid(SEQ / 64, BATCH * NH);     // (32, 64)
    flash_mma<<<fgrid, 128>>>(qhp, qlp, khp, klp, vhp, vlp, attn);

    split_kernel<<<(x4 + 255) / 256, 256>>>(attn, ah, al, x4);
    gemm_mma<<<ggrid, 256>>>(ah, al, wh + 3 * HID * HID, wl + 3 * HID * HID, out);
}

// round 13
// speedup vs baseline: 2.7977x; 1.3060x over previous
#include <cuda_runtime.h>
#include <cuda_bf16.h>
#include <math.h>
#include <stdint.h>

// Problem constants
#define BATCH 4
#define SEQ   2048
#define NH    16
#define HD    64
#define HID   1024           // NH*HD
#define MROWS (BATCH*SEQ)    // 8192

// ---------------------------------------------------------------------------
// mma.sync m16n8k16 bf16 (arch-portable HMMA; tcgen05 unavailable: harness
// targets family-generic sm_103, not sm_103a)
// ---------------------------------------------------------------------------
#define MMA16816(d, a, b) \
    asm volatile("mma.sync.aligned.m16n8k16.row.col.f32.bf16.bf16.f32 " \
        "{%0,%1,%2,%3}, {%4,%5,%6,%7}, {%8,%9}, {%0,%1,%2,%3};" \
        : "+f"((d)[0]), "+f"((d)[1]), "+f"((d)[2]), "+f"((d)[3]) \
        : "r"((a)[0]), "r"((a)[1]), "r"((a)[2]), "r"((a)[3]), \
          "r"((b)[0]), "r"((b)[1]))

__device__ __forceinline__ uint32_t smem_u32(const void* p) {
    uint32_t a;
    asm("{ .reg .u64 t; cvta.to.shared.u64 t, %1; cvt.u32.u64 %0, t; }"
        : "=r"(a) : "l"(p));
    return a;
}
__device__ __forceinline__ void cpa16(uint32_t s, const void* g) {
    asm volatile("cp.async.cg.shared.global [%0], [%1], 16;" :: "r"(s), "l"(g));
}
__device__ __forceinline__ void cp_commit() {
    asm volatile("cp.async.commit_group;" ::: "memory");
}
template<int N> __device__ __forceinline__ void cp_wait() {
    asm volatile("cp.async.wait_group %0;" :: "n"(N) : "memory");
}

// Split two fp32 into packed bf16 hi-pair and lo-pair (residual)
__device__ __forceinline__ void split_pack(float x, float y,
                                           uint32_t& hp, uint32_t& lp) {
    __nv_bfloat16 hx = __float2bfloat16(x);
    __nv_bfloat16 hy = __float2bfloat16(y);
    __nv_bfloat16 lx = __float2bfloat16(x - __bfloat162float(hx));
    __nv_bfloat16 ly = __float2bfloat16(y - __bfloat162float(hy));
    __nv_bfloat162 H; H.x = hx; H.y = hy;
    __nv_bfloat162 L; L.x = lx; L.y = ly;
    hp = *reinterpret_cast<uint32_t*>(&H);
    lp = *reinterpret_cast<uint32_t*>(&L);
}

// ---------------------------------------------------------------------------
// Scratch (allocation-free)
// ---------------------------------------------------------------------------
__device__ float g_q[MROWS * HID];
__device__ float g_k[MROWS * HID];
__device__ float g_v[MROWS * HID];
__device__ float g_attn[MROWS * HID];
__device__ __nv_bfloat16 g_xh[MROWS * HID];
__device__ __nv_bfloat16 g_xl[MROWS * HID];
__device__ __nv_bfloat16 g_wh[4 * HID * HID];
__device__ __nv_bfloat16 g_wl[4 * HID * HID];
__device__ __nv_bfloat16 g_ah[MROWS * HID];
__device__ __nv_bfloat16 g_al[MROWS * HID];
__device__ __nv_bfloat16 g_qh[MROWS * HID];
__device__ __nv_bfloat16 g_ql[MROWS * HID];
__device__ __nv_bfloat16 g_kh[MROWS * HID];
__device__ __nv_bfloat16 g_kl[MROWS * HID];
__device__ __nv_bfloat16 g_vh[MROWS * HID];   // V^T hi: [b][h][d][t]
__device__ __nv_bfloat16 g_vl[MROWS * HID];   // V^T lo: [b][h][d][t]

// ---------------------------------------------------------------------------
// Split fp32 -> bf16 hi + bf16 lo (residual)
// ---------------------------------------------------------------------------
__global__ void split_kernel(const float* __restrict__ in,
                             __nv_bfloat16* __restrict__ hi,
                             __nv_bfloat16* __restrict__ lo, int n4) {
    int i = blockIdx.x * blockDim.x + threadIdx.x;
    if (i >= n4) return;
    float4 f = reinterpret_cast<const float4*>(in)[i];
    __nv_bfloat16 h0 = __float2bfloat16(f.x);
    __nv_bfloat16 h1 = __float2bfloat16(f.y);
    __nv_bfloat16 h2 = __float2bfloat16(f.z);
    __nv_bfloat16 h3 = __float2bfloat16(f.w);
    __nv_bfloat16 l0 = __float2bfloat16(f.x - __bfloat162float(h0));
    __nv_bfloat16 l1 = __float2bfloat16(f.y - __bfloat162float(h1));
    __nv_bfloat16 l2 = __float2bfloat16(f.z - __bfloat162float(h2));
    __nv_bfloat16 l3 = __float2bfloat16(f.w - __bfloat162float(h3));
    __nv_bfloat162 hp0; hp0.x = h0; hp0.y = h1;
    __nv_bfloat162 hp1; hp1.x = h2; hp1.y = h3;
    __nv_bfloat162 lp0; lp0.x = l0; lp0.y = l1;
    __nv_bfloat162 lp1; lp1.x = l2; lp1.y = l3;
    reinterpret_cast<__nv_bfloat162*>(hi)[i * 2 + 0] = hp0;
    reinterpret_cast<__nv_bfloat162*>(hi)[i * 2 + 1] = hp1;
    reinterpret_cast<__nv_bfloat162*>(lo)[i * 2 + 0] = lp0;
    reinterpret_cast<__nv_bfloat162*>(lo)[i * 2 + 1] = lp1;
}

// ---------------------------------------------------------------------------
// RoPE + optional scale + bf16 hi/lo split
// ---------------------------------------------------------------------------
__global__ void rope_split(const float* __restrict__ src,
                           __nv_bfloat16* __restrict__ hi,
                           __nv_bfloat16* __restrict__ lo,
                           const float* __restrict__ cosT,
                           const float* __restrict__ sinT, float scale) {
    int idx = blockIdx.x * blockDim.x + threadIdx.x;
    if (idx >= MROWS * NH * 32) return;
    int d = idx & 31;
    int h = (idx >> 5) & (NH - 1);
    int m = idx >> 9;
    int t = m & (SEQ - 1);
    float c = cosT[t * HD + d];
    float s = sinT[t * HD + d];
    size_t base = (size_t)m * HID + h * HD + d;
    float x1 = src[base];
    float x2 = src[base + 32];
    float r1 = (x1 * c - x2 * s) * scale;
    float r2 = (x2 * c + x1 * s) * scale;
    __nv_bfloat16 h1 = __float2bfloat16(r1);
    __nv_bfloat16 h2 = __float2bfloat16(r2);
    hi[base]      = h1;
    hi[base + 32] = h2;
    lo[base]      = __float2bfloat16(r1 - __bfloat162float(h1));
    lo[base + 32] = __float2bfloat16(r2 - __bfloat162float(h2));
}

// ---------------------------------------------------------------------------
// V transpose + split: v[b,t,h*64+d] fp32 -> vT[b,h,d,t] bf16 hi/lo
// 32x32 smem tiles, coalesced both directions.
// ---------------------------------------------------------------------------
__global__ void vsplit_t(const float* __restrict__ v,
                         __nv_bfloat16* __restrict__ hT,
                         __nv_bfloat16* __restrict__ lT) {
    __shared__ float tile[32][33];
    int bhid = blockIdx.z;            // b*16+h
    int b = bhid >> 4, h = bhid & 15;
    int t0 = blockIdx.x * 32;
    int d0 = blockIdx.y * 32;
    int tx = threadIdx.x;             // 0..31
    int ty = threadIdx.y;             // 0..7
#pragma unroll
    for (int i = 0; i < 4; i++) {
        int t = t0 + ty + i * 8;
        tile[ty + i * 8][tx] = v[((size_t)(b * SEQ + t)) * HID + h * HD + d0 + tx];
    }
    __syncthreads();
#pragma unroll
    for (int i = 0; i < 4; i++) {
        int d = d0 + ty + i * 8;
        float f = tile[tx][ty + i * 8];
        __nv_bfloat16 hi = __float2bfloat16(f);
        size_t o = ((size_t)bhid * HD + d) * SEQ + t0 + tx;
        hT[o] = hi;
        lT[o] = __float2bfloat16(f - __bfloat162float(hi));
    }
}

// ---------------------------------------------------------------------------
// HMMA split-bf16 GEMM with cp.async double buffering.
// C[m,n] = sum_k A[m,k]*B[n,k]. Block 128x128, BK=32, 8 warps 4(m)x2(n).
// ---------------------------------------------------------------------------
#define GK 1024
#define GN 1024
#define LDSB 40
#define TILEG (128 * LDSB)                    // halves per tile
#define GEMM_SMEM (2 * 4 * TILEG * 2)         // bytes (2 stages x 4 tiles)

__global__ void __launch_bounds__(256) gemm_mma(
        const __nv_bfloat16* __restrict__ Ah, const __nv_bfloat16* __restrict__ Al,
        const __nv_bfloat16* __restrict__ Bh, const __nv_bfloat16* __restrict__ Bl,
        float* __restrict__ C) {
    extern __shared__ __nv_bfloat16 dsm[];
    const uint32_t sbase = smem_u32(dsm);

    const int tid  = threadIdx.x;
    const int warp = tid >> 5;
    const int lane = tid & 31;
    const int g    = lane >> 2;
    const int tig  = lane & 3;

    const int m0 = blockIdx.y * 128;
    const int n0 = blockIdx.x * 128;
    const int mbase = (warp & 3) * 32;
    const int nbase = (warp >> 2) * 64;

    const __nv_bfloat16* gsrc[4] = {Ah + (size_t)m0 * GK, Al + (size_t)m0 * GK,
                                    Bh + (size_t)n0 * GK, Bl + (size_t)n0 * GK};

    auto issue = [&](int k0, int buf) {
        uint32_t b0 = sbase + (uint32_t)buf * 4 * TILEG * 2;
        for (int s = tid; s < 512; s += 256) {
            int r = s >> 2;
            int c = (s & 3) * 8;
            uint32_t doff = (uint32_t)(r * LDSB + c) * 2;
#pragma unroll
            for (int t = 0; t < 4; t++)
                cpa16(b0 + (uint32_t)t * TILEG * 2 + doff,
                      gsrc[t] + (size_t)r * GK + k0 + c);
        }
        cp_commit();
    };

    float acc[2][8][4];
#pragma unroll
    for (int mf = 0; mf < 2; mf++)
#pragma unroll
        for (int nf = 0; nf < 8; nf++)
#pragma unroll
            for (int c = 0; c < 4; c++) acc[mf][nf][c] = 0.f;

    issue(0, 0);

    for (int kt = 0; kt < 32; kt++) {
        if (kt < 31) issue((kt + 1) * 32, (kt + 1) & 1);
        if (kt < 31) cp_wait<1>(); else cp_wait<0>();
        __syncthreads();

        __nv_bfloat16* sAh = dsm + (size_t)(kt & 1) * 4 * TILEG;
        __nv_bfloat16* sAl = sAh + TILEG;
        __nv_bfloat16* sBh = sAh + 2 * TILEG;
        __nv_bfloat16* sBl = sAh + 3 * TILEG;

#pragma unroll
        for (int kk = 0; kk < 32; kk += 16) {
            uint32_t ah[2][4], al[2][4], bh[8][2], bl[8][2];
#pragma unroll
            for (int mf = 0; mf < 2; mf++) {
                int row = mbase + mf * 16 + g;
                int col = kk + tig * 2;
                ah[mf][0] = *reinterpret_cast<uint32_t*>(&sAh[row * LDSB + col]);
                ah[mf][1] = *reinterpret_cast<uint32_t*>(&sAh[(row + 8) * LDSB + col]);
                ah[mf][2] = *reinterpret_cast<uint32_t*>(&sAh[row * LDSB + col + 8]);
                ah[mf][3] = *reinterpret_cast<uint32_t*>(&sAh[(row + 8) * LDSB + col + 8]);
                al[mf][0] = *reinterpret_cast<uint32_t*>(&sAl[row * LDSB + col]);
                al[mf][1] = *reinterpret_cast<uint32_t*>(&sAl[(row + 8) * LDSB + col]);
                al[mf][2] = *reinterpret_cast<uint32_t*>(&sAl[row * LDSB + col + 8]);
                al[mf][3] = *reinterpret_cast<uint32_t*>(&sAl[(row + 8) * LDSB + col + 8]);
            }
#pragma unroll
            for (int nf = 0; nf < 8; nf++) {
                int row = nbase + nf * 8 + g;
                int col = kk + tig * 2;
                bh[nf][0] = *reinterpret_cast<uint32_t*>(&sBh[row * LDSB + col]);
                bh[nf][1] = *reinterpret_cast<uint32_t*>(&sBh[row * LDSB + col + 8]);
                bl[nf][0] = *reinterpret_cast<uint32_t*>(&sBl[row * LDSB + col]);
                bl[nf][1] = *reinterpret_cast<uint32_t*>(&sBl[row * LDSB + col + 8]);
            }
#pragma unroll
            for (int mf = 0; mf < 2; mf++)
#pragma unroll
                for (int nf = 0; nf < 8; nf++) {
                    MMA16816(acc[mf][nf], ah[mf], bh[nf]);
                    MMA16816(acc[mf][nf], ah[mf], bl[nf]);
                    MMA16816(acc[mf][nf], al[mf], bh[nf]);
                }
        }
        __syncthreads();
    }

#pragma unroll
    for (int mf = 0; mf < 2; mf++) {
#pragma unroll
        for (int nf = 0; nf < 8; nf++) {
            int row = m0 + mbase + mf * 16 + g;
            int col = n0 + nbase + nf * 8 + tig * 2;
            *reinterpret_cast<float2*>(C + (size_t)row * GN + col) =
                make_float2(acc[mf][nf][0], acc[mf][nf][1]);
            *reinterpret_cast<float2*>(C + (size_t)(row + 8) * GN + col) =
                make_float2(acc[mf][nf][2], acc[mf][nf][3]);
        }
    }
}

// ---------------------------------------------------------------------------
// HMMA flash attention with cp.async double-buffered K and V^T tiles.
// 4 warps, 64-query tile, causal. Q pre-scaled & split (rope_split).
// V^T precomputed globally (vsplit_t) -> tile loads are plain copies.
// ---------------------------------------------------------------------------
#define AT_STR 72
#define TILEA (64 * AT_STR)                   // halves per tile
#define FLASH_SMEM (2 * 4 * TILEA * 2)        // bytes (2 stages x 4 tiles)

__global__ void __launch_bounds__(128) flash_mma(
        const __nv_bfloat16* __restrict__ qh, const __nv_bfloat16* __restrict__ ql,
        const __nv_bfloat16* __restrict__ kh, const __nv_bfloat16* __restrict__ kl,
        const __nv_bfloat16* __restrict__ vhT, const __nv_bfloat16* __restrict__ vlT,
        float* __restrict__ o) {
    extern __shared__ __nv_bfloat16 fsm[];
    const uint32_t sbase = smem_u32(fsm);

    const int qt = blockIdx.x;
    const int bhid = blockIdx.y;
    const int b = bhid >> 4;
    const int h = bhid & 15;
    const int tid = threadIdx.x;
    const int w = tid >> 5;
    const int lane = tid & 31;
    const int g = lane >> 2;
    const int tig = lane & 3;

    const size_t baseQ  = ((size_t)b * SEQ + qt * 64) * HID + h * HD;
    const size_t baseKV = (size_t)b * SEQ * HID + h * HD;
    const size_t baseVT = (size_t)bhid * HD * SEQ;

    // Stage Q (row-major q x d) into buffer-0 area, extract persistent frags
    {
        __nv_bfloat16* sQh = fsm;
        __nv_bfloat16* sQl = fsm + TILEA;
        for (int s = tid; s < 512; s += 128) {
            int r = s >> 3;
            int c8 = (s & 7) * 8;
            *reinterpret_cast<uint4*>(&sQh[r * AT_STR + c8]) =
                *reinterpret_cast<const uint4*>(qh + baseQ + (size_t)r * HID + c8);
            *reinterpret_cast<uint4*>(&sQl[r * AT_STR + c8]) =
                *reinterpret_cast<const uint4*>(ql + baseQ + (size_t)r * HID + c8);
        }
    }
    __syncthreads();

    uint32_t qfh[4][4], qfl[4][4];
    {
        __nv_bfloat16* sQh = fsm;
        __nv_bfloat16* sQl = fsm + TILEA;
        int row = w * 16 + g;
#pragma unroll
        for (int kc = 0; kc < 4; kc++) {
            int c = kc * 16 + tig * 2;
            qfh[kc][0] = *reinterpret_cast<uint32_t*>(&sQh[row * AT_STR + c]);
            qfh[kc][1] = *reinterpret_cast<uint32_t*>(&sQh[(row + 8) * AT_STR + c]);
            qfh[kc][2] = *reinterpret_cast<uint32_t*>(&sQh[row * AT_STR + c + 8]);
            qfh[kc][3] = *reinterpret_cast<uint32_t*>(&sQh[(row + 8) * AT_STR + c + 8]);
            qfl[kc][0] = *reinterpret_cast<uint32_t*>(&sQl[row * AT_STR + c]);
            qfl[kc][1] = *reinterpret_cast<uint32_t*>(&sQl[(row + 8) * AT_STR + c]);
            qfl[kc][2] = *reinterpret_cast<uint32_t*>(&sQl[row * AT_STR + c + 8]);
            qfl[kc][3] = *reinterpret_cast<uint32_t*>(&sQl[(row + 8) * AT_STR + c + 8]);
        }
    }
    __syncthreads();

    auto issue = [&](int jt, int buf) {
        uint32_t b0 = sbase + (uint32_t)buf * 4 * TILEA * 2;
        const __nv_bfloat16* kbh = kh + baseKV + (size_t)jt * 64 * HID;
        const __nv_bfloat16* kbl = kl + baseKV + (size_t)jt * 64 * HID;
        const __nv_bfloat16* vbh = vhT + baseVT + jt * 64;
        const __nv_bfloat16* vbl = vlT + baseVT + jt * 64;
        for (int s = tid; s < 512; s += 128) {
            int r = s >> 3;
            int c8 = (s & 7) * 8;
            uint32_t doff = (uint32_t)(r * AT_STR + c8) * 2;
            cpa16(b0 + 0u * TILEA * 2 + doff, kbh + (size_t)r * HID + c8);
            cpa16(b0 + 1u * TILEA * 2 + doff, kbl + (size_t)r * HID + c8);
            cpa16(b0 + 2u * TILEA * 2 + doff, vbh + (size_t)r * SEQ + c8);
            cpa16(b0 + 3u * TILEA * 2 + doff, vbl + (size_t)r * SEQ + c8);
        }
        cp_commit();
    };

    float O[8][4];
#pragma unroll
    for (int nf = 0; nf < 8; nf++)
#pragma unroll
        for (int c = 0; c < 4; c++) O[nf][c] = 0.f;
    float m0 = -INFINITY, m1 = -INFINITY, l0 = 0.f, l1 = 0.f;

    issue(0, 0);

    for (int jt = 0; jt <= qt; jt++) {
        if (jt < qt) issue(jt + 1, (jt + 1) & 1);
        if (jt < qt) cp_wait<1>(); else cp_wait<0>();
        __syncthreads();

        __nv_bfloat16* sKh = fsm + (size_t)(jt & 1) * 4 * TILEA;
        __nv_bfloat16* sKl = sKh + TILEA;
        __nv_bfloat16* sVh = sKh + 2 * TILEA;
        __nv_bfloat16* sVl = sKh + 3 * TILEA;

        // S = Q K^T (16x64 per warp), 3-pass split
        float S[8][4];
#pragma unroll
        for (int nf = 0; nf < 8; nf++)
#pragma unroll
            for (int c = 0; c < 4; c++) S[nf][c] = 0.f;

#pragma unroll
        for (int nf = 0; nf < 8; nf++) {
            int rowb = nf * 8 + g;
#pragma unroll
            for (int kc = 0; kc < 4; kc++) {
                int c = kc * 16 + tig * 2;
                uint32_t bkh[2], bkl[2];
                bkh[0] = *reinterpret_cast<uint32_t*>(&sKh[rowb * AT_STR + c]);
                bkh[1] = *reinterpret_cast<uint32_t*>(&sKh[rowb * AT_STR + c + 8]);
                bkl[0] = *reinterpret_cast<uint32_t*>(&sKl[rowb * AT_STR + c]);
                bkl[1] = *reinterpret_cast<uint32_t*>(&sKl[rowb * AT_STR + c + 8]);
                MMA16816(S[nf], qfh[kc], bkh);
                MMA16816(S[nf], qfh[kc], bkl);
                MMA16816(S[nf], qfl[kc], bkh);
            }
        }

        if (jt == qt) {
            int lr0 = w * 16 + g;
            int lr1 = lr0 + 8;
#pragma unroll
            for (int nf = 0; nf < 8; nf++) {
                int jc = nf * 8 + tig * 2;
                if (jc > lr0)     S[nf][0] = -INFINITY;
                if (jc + 1 > lr0) S[nf][1] = -INFINITY;
                if (jc > lr1)     S[nf][2] = -INFINITY;
                if (jc + 1 > lr1) S[nf][3] = -INFINITY;
            }
        }

        // Online softmax (quad shfl)
        float mx0 = -INFINITY, mx1 = -INFINITY;
#pragma unroll
        for (int nf = 0; nf < 8; nf++) {
            mx0 = fmaxf(mx0, fmaxf(S[nf][0], S[nf][1]));
            mx1 = fmaxf(mx1, fmaxf(S[nf][2], S[nf][3]));
        }
        mx0 = fmaxf(mx0, __shfl_xor_sync(0xFFFFFFFF, mx0, 1));
        mx0 = fmaxf(mx0, __shfl_xor_sync(0xFFFFFFFF, mx0, 2));
        mx1 = fmaxf(mx1, __shfl_xor_sync(0xFFFFFFFF, mx1, 1));
        mx1 = fmaxf(mx1, __shfl_xor_sync(0xFFFFFFFF, mx1, 2));
        float nm0 = fmaxf(m0, mx0);
        float nm1 = fmaxf(m1, mx1);
        float corr0 = __expf(m0 - nm0);
        float corr1 = __expf(m1 - nm1);
        m0 = nm0; m1 = nm1;
        float sum0 = 0.f, sum1 = 0.f;
#pragma unroll
        for (int nf = 0; nf < 8; nf++) {
            S[nf][0] = __expf(S[nf][0] - m0); sum0 += S[nf][0];
            S[nf][1] = __expf(S[nf][1] - m0); sum0 += S[nf][1];
            S[nf][2] = __expf(S[nf][2] - m1); sum1 += S[nf][2];
            S[nf][3] = __expf(S[nf][3] - m1); sum1 += S[nf][3];
        }
        sum0 += __shfl_xor_sync(0xFFFFFFFF, sum0, 1);
        sum0 += __shfl_xor_sync(0xFFFFFFFF, sum0, 2);
        sum1 += __shfl_xor_sync(0xFFFFFFFF, sum1, 1);
        sum1 += __shfl_xor_sync(0xFFFFFFFF, sum1, 2);
        l0 = l0 * corr0 + sum0;
        l1 = l1 * corr1 + sum1;
#pragma unroll
        for (int nf = 0; nf < 8; nf++) {
            O[nf][0] *= corr0; O[nf][1] *= corr0;
            O[nf][2] *= corr1; O[nf][3] *= corr1;
        }

        // S (C-frag) -> P A-frags (hi/lo) in registers
        uint32_t aPh[4][4], aPl[4][4];
#pragma unroll
        for (int kc = 0; kc < 4; kc++) {
            split_pack(S[2 * kc][0],     S[2 * kc][1],     aPh[kc][0], aPl[kc][0]);
            split_pack(S[2 * kc][2],     S[2 * kc][3],     aPh[kc][1], aPl[kc][1]);
            split_pack(S[2 * kc + 1][0], S[2 * kc + 1][1], aPh[kc][2], aPl[kc][2]);
            split_pack(S[2 * kc + 1][2], S[2 * kc + 1][3], aPh[kc][3], aPl[kc][3]);
        }

        // O += P @ V (V^T tiles), 3-pass split
#pragma unroll
        for (int nf = 0; nf < 8; nf++) {
            int rowb = nf * 8 + g;
#pragma unroll
            for (int kc = 0; kc < 4; kc++) {
                int c = kc * 16 + tig * 2;
                uint32_t bvh[2], bvl[2];
                bvh[0] = *reinterpret_cast<uint32_t*>(&sVh[rowb * AT_STR + c]);
                bvh[1] = *reinterpret_cast<uint32_t*>(&sVh[rowb * AT_STR + c + 8]);
                bvl[0] = *reinterpret_cast<uint32_t*>(&sVl[rowb * AT_STR + c]);
                bvl[1] = *reinterpret_cast<uint32_t*>(&sVl[rowb * AT_STR + c + 8]);
                MMA16816(O[nf], aPh[kc], bvh);
                MMA16816(O[nf], aPh[kc], bvl);
                MMA16816(O[nf], aPl[kc], bvh);
            }
        }
        __syncthreads();
    }

    float inv0 = 1.f / l0;
    float inv1 = 1.f / l1;
    int row0 = qt * 64 + w * 16 + g;
#pragma unroll
    for (int nf = 0; nf < 8; nf++) {
        int col = nf * 8 + tig * 2;
        *reinterpret_cast<float2*>(o + ((size_t)b * SEQ + row0) * HID + h * HD + col) =
            make_float2(O[nf][0] * inv0, O[nf][1] * inv0);
        *reinterpret_cast<float2*>(o + ((size_t)b * SEQ + row0 + 8) * HID + h * HD + col) =
            make_float2(O[nf][2] * inv1, O[nf][3] * inv1);
    }
}

// ---------------------------------------------------------------------------
// Launch
// ---------------------------------------------------------------------------
extern "C" void kernel_launch(void* const* d_in, const int* in_sizes, int n_in,
                              void* d_out, int out_size) {
    const float* x    = (const float*)d_in[0];
    const float* cosT = (const float*)d_in[1];
    const float* sinT = (const float*)d_in[2];
    const float* wq   = (const float*)d_in[3];
    const float* wk   = (const float*)d_in[4];
    const float* wv   = (const float*)d_in[5];
    const float* wo   = (const float*)d_in[6];
    float* out = (float*)d_out;

    float *q, *k, *v, *attn;
    __nv_bfloat16 *xh, *xl, *wh, *wl, *ah, *al;
    __nv_bfloat16 *qhp, *qlp, *khp, *klp, *vhp, *vlp;
    cudaGetSymbolAddress((void**)&q, g_q);
    cudaGetSymbolAddress((void**)&k, g_k);
    cudaGetSymbolAddress((void**)&v, g_v);
    cudaGetSymbolAddress((void**)&attn, g_attn);
    cudaGetSymbolAddress((void**)&xh, g_xh);
    cudaGetSymbolAddress((void**)&xl, g_xl);
    cudaGetSymbolAddress((void**)&wh, g_wh);
    cudaGetSymbolAddress((void**)&wl, g_wl);
    cudaGetSymbolAddress((void**)&ah, g_ah);
    cudaGetSymbolAddress((void**)&al, g_al);
    cudaGetSymbolAddress((void**)&qhp, g_qh);
    cudaGetSymbolAddress((void**)&qlp, g_ql);
    cudaGetSymbolAddress((void**)&khp, g_kh);
    cudaGetSymbolAddress((void**)&klp, g_kl);
    cudaGetSymbolAddress((void**)&vhp, g_vh);
    cudaGetSymbolAddress((void**)&vlp, g_vl);

    cudaFuncSetAttribute(gemm_mma, cudaFuncAttributeMaxDynamicSharedMemorySize,
                         GEMM_SMEM);
    cudaFuncSetAttribute(flash_mma, cudaFuncAttributeMaxDynamicSharedMemorySize,
                         FLASH_SMEM);

    // Split inputs to bf16 hi/lo
    int x4 = MROWS * HID / 4;
    int w4 = HID * HID / 4;
    split_kernel<<<(x4 + 255) / 256, 256>>>(x, xh, xl, x4);
    split_kernel<<<(w4 + 255) / 256, 256>>>(wq, wh + 0 * HID * HID, wl + 0 * HID * HID, w4);
    split_kernel<<<(w4 + 255) / 256, 256>>>(wk, wh + 1 * HID * HID, wl + 1 * HID * HID, w4);
    split_kernel<<<(w4 + 255) / 256, 256>>>(wv, wh + 2 * HID * HID, wl + 2 * HID * HID, w4);
    split_kernel<<<(w4 + 255) / 256, 256>>>(wo, wh + 3 * HID * HID, wl + 3 * HID * HID, w4);

    dim3 ggrid(HID / 128, MROWS / 128);   // (8, 64)
    gemm_mma<<<ggrid, 256, GEMM_SMEM>>>(xh, xl, wh + 0 * HID * HID, wl + 0 * HID * HID, q);
    gemm_mma<<<ggrid, 256, GEMM_SMEM>>>(xh, xl, wh + 1 * HID * HID, wl + 1 * HID * HID, k);
    gemm_mma<<<ggrid, 256, GEMM_SMEM>>>(xh, xl, wh + 2 * HID * HID, wl + 2 * HID * HID, v);

    // RoPE + scale(Q) + split; V transpose+split to [b,h,d,t]
    int rope_n = MROWS * NH * 32;
    rope_split<<<(rope_n + 255) / 256, 256>>>(q, qhp, qlp, cosT, sinT, 0.125f);
    rope_split<<<(rope_n + 255) / 256, 256>>>(k, khp, klp, cosT, sinT, 1.0f);
    vsplit_t<<<dim3(SEQ / 32, HD / 32, BATCH * NH), dim3(32, 8)>>>(v, vhp, vlp);

    dim3 fgrid(SEQ / 64, BATCH * NH);     // (32, 64)
    flash_mma<<<fgrid, 128, FLASH_SMEM>>>(qhp, qlp, khp, klp, vhp, vlp, attn);

    split_kernel<<<(x4 + 255) / 256, 256>>>(attn, ah, al, x4);
    gemm_mma<<<ggrid, 256, GEMM_SMEM>>>(ah, al, wh + 3 * HID * HID, wl + 3 * HID * HID, out);
}

// round 15
// speedup vs baseline: 2.8402x; 1.0152x over previous
#include <cuda_runtime.h>
#include <cuda_bf16.h>
#include <math.h>
#include <stdint.h>

// Problem constants
#define BATCH 4
#define SEQ   2048
#define NH    16
#define HD    64
#define HID   1024           // NH*HD
#define MROWS (BATCH*SEQ)    // 8192

// ---------------------------------------------------------------------------
// mma.sync m16n8k16 bf16 (arch-portable HMMA; tcgen05 unavailable: harness
// targets family-generic sm_103, not sm_103a)
// ---------------------------------------------------------------------------
#define MMA16816(d, a, b) \
    asm volatile("mma.sync.aligned.m16n8k16.row.col.f32.bf16.bf16.f32 " \
        "{%0,%1,%2,%3}, {%4,%5,%6,%7}, {%8,%9}, {%0,%1,%2,%3};" \
        : "+f"((d)[0]), "+f"((d)[1]), "+f"((d)[2]), "+f"((d)[3]) \
        : "r"((a)[0]), "r"((a)[1]), "r"((a)[2]), "r"((a)[3]), \
          "r"((b)[0]), "r"((b)[1]))

__device__ __forceinline__ uint32_t smem_u32(const void* p) {
    uint32_t a;
    asm("{ .reg .u64 t; cvta.to.shared.u64 t, %1; cvt.u32.u64 %0, t; }"
        : "=r"(a) : "l"(p));
    return a;
}
__device__ __forceinline__ void cpa16(uint32_t s, const void* g) {
    asm volatile("cp.async.cg.shared.global [%0], [%1], 16;" :: "r"(s), "l"(g));
}
__device__ __forceinline__ void cp_commit() {
    asm volatile("cp.async.commit_group;" ::: "memory");
}
template<int N> __device__ __forceinline__ void cp_wait() {
    asm volatile("cp.async.wait_group %0;" :: "n"(N) : "memory");
}

// Split two fp32 into packed bf16 hi-pair and lo-pair (residual)
__device__ __forceinline__ void split_pack(float x, float y,
                                           uint32_t& hp, uint32_t& lp) {
    __nv_bfloat16 hx = __float2bfloat16(x);
    __nv_bfloat16 hy = __float2bfloat16(y);
    __nv_bfloat16 lx = __float2bfloat16(x - __bfloat162float(hx));
    __nv_bfloat16 ly = __float2bfloat16(y - __bfloat162float(hy));
    __nv_bfloat162 H; H.x = hx; H.y = hy;
    __nv_bfloat162 L; L.x = lx; L.y = ly;
    hp = *reinterpret_cast<uint32_t*>(&H);
    lp = *reinterpret_cast<uint32_t*>(&L);
}

// ---------------------------------------------------------------------------
// Scratch (allocation-free)
// ---------------------------------------------------------------------------
__device__ float g_v[MROWS * HID];
__device__ __nv_bfloat16 g_xh[MROWS * HID];
__device__ __nv_bfloat16 g_xl[MROWS * HID];
__device__ __nv_bfloat16 g_wh[4 * HID * HID];
__device__ __nv_bfloat16 g_wl[4 * HID * HID];
__device__ __nv_bfloat16 g_ah[MROWS * HID];
__device__ __nv_bfloat16 g_al[MROWS * HID];
__device__ __nv_bfloat16 g_qh[MROWS * HID];
__device__ __nv_bfloat16 g_ql[MROWS * HID];
__device__ __nv_bfloat16 g_kh[MROWS * HID];
__device__ __nv_bfloat16 g_kl[MROWS * HID];
__device__ __nv_bfloat16 g_vh[MROWS * HID];   // V^T hi: [b][h][d][t]
__device__ __nv_bfloat16 g_vl[MROWS * HID];   // V^T lo: [b][h][d][t]

// ---------------------------------------------------------------------------
// Split fp32 -> bf16 hi + bf16 lo (residual)
// ---------------------------------------------------------------------------
__global__ void split_kernel(const float* __restrict__ in,
                             __nv_bfloat16* __restrict__ hi,
                             __nv_bfloat16* __restrict__ lo, int n4) {
    int i = blockIdx.x * blockDim.x + threadIdx.x;
    if (i >= n4) return;
    float4 f = reinterpret_cast<const float4*>(in)[i];
    __nv_bfloat16 h0 = __float2bfloat16(f.x);
    __nv_bfloat16 h1 = __float2bfloat16(f.y);
    __nv_bfloat16 h2 = __float2bfloat16(f.z);
    __nv_bfloat16 h3 = __float2bfloat16(f.w);
    __nv_bfloat16 l0 = __float2bfloat16(f.x - __bfloat162float(h0));
    __nv_bfloat16 l1 = __float2bfloat16(f.y - __bfloat162float(h1));
    __nv_bfloat16 l2 = __float2bfloat16(f.z - __bfloat162float(h2));
    __nv_bfloat16 l3 = __float2bfloat16(f.w - __bfloat162float(h3));
    __nv_bfloat162 hp0; hp0.x = h0; hp0.y = h1;
    __nv_bfloat162 hp1; hp1.x = h2; hp1.y = h3;
    __nv_bfloat162 lp0; lp0.x = l0; lp0.y = l1;
    __nv_bfloat162 lp1; lp1.x = l2; lp1.y = l3;
    reinterpret_cast<__nv_bfloat162*>(hi)[i * 2 + 0] = hp0;
    reinterpret_cast<__nv_bfloat162*>(hi)[i * 2 + 1] = hp1;
    reinterpret_cast<__nv_bfloat162*>(lo)[i * 2 + 0] = lp0;
    reinterpret_cast<__nv_bfloat162*>(lo)[i * 2 + 1] = lp1;
}

// ---------------------------------------------------------------------------
// V transpose + split: v[b,t,h*64+d] fp32 -> vT[b,h,d,t] bf16 hi/lo
// ---------------------------------------------------------------------------
__global__ void vsplit_t(const float* __restrict__ v,
                         __nv_bfloat16* __restrict__ hT,
                         __nv_bfloat16* __restrict__ lT) {
    __shared__ float tile[32][33];
    int bhid = blockIdx.z;            // b*16+h
    int b = bhid >> 4, h = bhid & 15;
    int t0 = blockIdx.x * 32;
    int d0 = blockIdx.y * 32;
    int tx = threadIdx.x;
    int ty = threadIdx.y;
#pragma unroll
    for (int i = 0; i < 4; i++) {
        int t = t0 + ty + i * 8;
        tile[ty + i * 8][tx] = v[((size_t)(b * SEQ + t)) * HID + h * HD + d0 + tx];
    }
    __syncthreads();
#pragma unroll
    for (int i = 0; i < 4; i++) {
        int d = d0 + ty + i * 8;
        float f = tile[tx][ty + i * 8];
        __nv_bfloat16 hi = __float2bfloat16(f);
        size_t o = ((size_t)bhid * HD + d) * SEQ + t0 + tx;
        hT[o] = hi;
        lT[o] = __float2bfloat16(f - __bfloat162float(hi));
    }
}

// ---------------------------------------------------------------------------
// HMMA split-bf16 GEMM with cp.async double buffering.
// MODE 0: write fp32 C.
// MODE 1: fused RoPE(+scale) + bf16 hi/lo split epilogue -> Oh/Ol.
//         (rope pair (d, d+32) = acc nf and nf+4 of the same thread)
// ---------------------------------------------------------------------------
#define GK 1024
#define GN 1024
#define LDSB 40
#define TILEG (128 * LDSB)                    // halves per tile
#define GEMM_SMEM (2 * 4 * TILEG * 2)         // bytes (2 stages x 4 tiles)

template<int MODE>
__global__ void __launch_bounds__(256) gemm_mma(
        const __nv_bfloat16* __restrict__ Ah, const __nv_bfloat16* __restrict__ Al,
        const __nv_bfloat16* __restrict__ Bh, const __nv_bfloat16* __restrict__ Bl,
        float* __restrict__ C,
        __nv_bfloat16* __restrict__ Oh, __nv_bfloat16* __restrict__ Ol,
        const float* __restrict__ cosT, const float* __restrict__ sinT,
        float scale) {
    extern __shared__ __nv_bfloat16 dsm[];
    const uint32_t sbase = smem_u32(dsm);

    const int tid  = threadIdx.x;
    const int warp = tid >> 5;
    const int lane = tid & 31;
    const int g    = lane >> 2;
    const int tig  = lane & 3;

    const int m0 = blockIdx.y * 128;
    const int n0 = blockIdx.x * 128;
    const int mbase = (warp & 3) * 32;
    const int nbase = (warp >> 2) * 64;

    const __nv_bfloat16* gsrc[4] = {Ah + (size_t)m0 * GK, Al + (size_t)m0 * GK,
                                    Bh + (size_t)n0 * GK, Bl + (size_t)n0 * GK};

    auto issue = [&](int k0, int buf) {
        uint32_t b0 = sbase + (uint32_t)buf * 4 * TILEG * 2;
        for (int s = tid; s < 512; s += 256) {
            int r = s >> 2;
            int c = (s & 3) * 8;
            uint32_t doff = (uint32_t)(r * LDSB + c) * 2;
#pragma unroll
            for (int t = 0; t < 4; t++)
                cpa16(b0 + (uint32_t)t * TILEG * 2 + doff,
                      gsrc[t] + (size_t)r * GK + k0 + c);
        }
        cp_commit();
    };

    float acc[2][8][4];
#pragma unroll
    for (int mf = 0; mf < 2; mf++)
#pragma unroll
        for (int nf = 0; nf < 8; nf++)
#pragma unroll
            for (int c = 0; c < 4; c++) acc[mf][nf][c] = 0.f;

    issue(0, 0);

    for (int kt = 0; kt < 32; kt++) {
        if (kt < 31) issue((kt + 1) * 32, (kt + 1) & 1);
        if (kt < 31) cp_wait<1>(); else cp_wait<0>();
        __syncthreads();

        __nv_bfloat16* sAh = dsm + (size_t)(kt & 1) * 4 * TILEG;
        __nv_bfloat16* sAl = sAh + TILEG;
        __nv_bfloat16* sBh = sAh + 2 * TILEG;
        __nv_bfloat16* sBl = sAh + 3 * TILEG;

#pragma unroll
        for (int kk = 0; kk < 32; kk += 16) {
            uint32_t ah[2][4], al[2][4], bh[8][2], bl[8][2];
#pragma unroll
            for (int mf = 0; mf < 2; mf++) {
                int row = mbase + mf * 16 + g;
                int col = kk + tig * 2;
                ah[mf][0] = *reinterpret_cast<uint32_t*>(&sAh[row * LDSB + col]);
                ah[mf][1] = *reinterpret_cast<uint32_t*>(&sAh[(row + 8) * LDSB + col]);
                ah[mf][2] = *reinterpret_cast<uint32_t*>(&sAh[row * LDSB + col + 8]);
                ah[mf][3] = *reinterpret_cast<uint32_t*>(&sAh[(row + 8) * LDSB + col + 8]);
                al[mf][0] = *reinterpret_cast<uint32_t*>(&sAl[row * LDSB + col]);
                al[mf][1] = *reinterpret_cast<uint32_t*>(&sAl[(row + 8) * LDSB + col]);
                al[mf][2] = *reinterpret_cast<uint32_t*>(&sAl[row * LDSB + col + 8]);
                al[mf][3] = *reinterpret_cast<uint32_t*>(&sAl[(row + 8) * LDSB + col + 8]);
            }
#pragma unroll
            for (int nf = 0; nf < 8; nf++) {
                int row = nbase + nf * 8 + g;
                int col = kk + tig * 2;
                bh[nf][0] = *reinterpret_cast<uint32_t*>(&sBh[row * LDSB + col]);
                bh[nf][1] = *reinterpret_cast<uint32_t*>(&sBh[row * LDSB + col + 8]);
                bl[nf][0] = *reinterpret_cast<uint32_t*>(&sBl[row * LDSB + col]);
                bl[nf][1] = *reinterpret_cast<uint32_t*>(&sBl[row * LDSB + col + 8]);
            }
#pragma unroll
            for (int mf = 0; mf < 2; mf++)
#pragma unroll
                for (int nf = 0; nf < 8; nf++) {
                    MMA16816(acc[mf][nf], ah[mf], bh[nf]);
                    MMA16816(acc[mf][nf], ah[mf], bl[nf]);
                    MMA16816(acc[mf][nf], al[mf], bh[nf]);
                }
        }
        __syncthreads();
    }

    if (MODE == 0) {
#pragma unroll
        for (int mf = 0; mf < 2; mf++) {
#pragma unroll
            for (int nf = 0; nf < 8; nf++) {
                int row = m0 + mbase + mf * 16 + g;
                int col = n0 + nbase + nf * 8 + tig * 2;
                *reinterpret_cast<float2*>(C + (size_t)row * GN + col) =
                    make_float2(acc[mf][nf][0], acc[mf][nf][1]);
                *reinterpret_cast<float2*>(C + (size_t)(row + 8) * GN + col) =
                    make_float2(acc[mf][nf][2], acc[mf][nf][3]);
            }
        }
    } else {
        // Fused RoPE + scale + split. acc[mf][nf] (d<32) pairs with acc[mf][nf+4]
        // (d+32). cos/sin indexed cosT[t*HD + d] with t = row % SEQ.
#pragma unroll
        for (int mf = 0; mf < 2; mf++) {
            int r0 = m0 + mbase + mf * 16 + g;
            int r1 = r0 + 8;
            int t0 = r0 & (SEQ - 1);
            int t1 = r1 & (SEQ - 1);
#pragma unroll
            for (int nf = 0; nf < 4; nf++) {
                int d = nf * 8 + tig * 2;           // head-local, < 32
                int col = n0 + nbase + d;           // global column of d
                float ca0 = cosT[t0 * HD + d],  ca1 = cosT[t0 * HD + d + 1];
                float sa0 = sinT[t0 * HD + d],  sa1 = sinT[t0 * HD + d + 1];
                float cb0 = cosT[t1 * HD + d],  cb1 = cosT[t1 * HD + d + 1];
                float sb0 = sinT[t1 * HD + d],  sb1 = sinT[t1 * HD + d + 1];
                float* a = acc[mf][nf];
                float* b = acc[mf][nf + 4];
                uint32_t hp, lp;
                // row r0, d and d+32
                split_pack((a[0] * ca0 - b[0] * sa0) * scale,
                           (a[1] * ca1 - b[1] * sa1) * scale, hp, lp);
                *reinterpret_cast<uint32_t*>(&Oh[(size_t)r0 * HID + col]) = hp;
                *reinterpret_cast<uint32_t*>(&Ol[(size_t)r0 * HID + col]) = lp;
                split_pack((b[0] * ca0 + a[0] * sa0) * scale,
                           (b[1] * ca1 + a[1] * sa1) * scale, hp, lp);
                *reinterpret_cast<uint32_t*>(&Oh[(size_t)r0 * HID + col + 32]) = hp;
                *reinterpret_cast<uint32_t*>(&Ol[(size_t)r0 * HID + col + 32]) = lp;
                // row r1
                split_pack((a[2] * cb0 - b[2] * sb0) * scale,
                           (a[3] * cb1 - b[3] * sb1) * scale, hp, lp);
                *reinterpret_cast<uint32_t*>(&Oh[(size_t)r1 * HID + col]) = hp;
                *reinterpret_cast<uint32_t*>(&Ol[(size_t)r1 * HID + col]) = lp;
                split_pack((b[2] * cb0 + a[2] * sb0) * scale,
                           (b[3] * cb1 + a[3] * sb1) * scale, hp, lp);
                *reinterpret_cast<uint32_t*>(&Oh[(size_t)r1 * HID + col + 32]) = hp;
                *reinterpret_cast<uint32_t*>(&Ol[(size_t)r1 * HID + col + 32]) = lp;
            }
        }
    }
}

// ---------------------------------------------------------------------------
// HMMA flash attention: 128-query tile, 8 warps, causal, double-buffered
// cp.async K/V^T, heavy-tiles-first launch order. Writes split-bf16 output.
// ---------------------------------------------------------------------------
#define AT_STR 72
#define TILEA (64 * AT_STR)                   // halves per 64-row tile
#define FLASH_SMEM (2 * 4 * TILEA * 2)        // bytes (2 stages x 4 tiles)

__global__ void __launch_bounds__(256) flash_mma(
        const __nv_bfloat16* __restrict__ qh, const __nv_bfloat16* __restrict__ ql,
        const __nv_bfloat16* __restrict__ kh, const __nv_bfloat16* __restrict__ kl,
        const __nv_bfloat16* __restrict__ vhT, const __nv_bfloat16* __restrict__ vlT,
        __nv_bfloat16* __restrict__ oh, __nv_bfloat16* __restrict__ ol) {
    extern __shared__ __nv_bfloat16 fsm[];
    const uint32_t sbase = smem_u32(fsm);

    const int qt = (gridDim.x - 1) - blockIdx.x;   // heavy blocks first
    const int bhid = blockIdx.y;
    const int b = bhid >> 4;
    const int h = bhid & 15;
    const int tid = threadIdx.x;
    const int w = tid >> 5;
    const int lane = tid & 31;
    const int g = lane >> 2;
    const int tig = lane & 3;

    const size_t baseQ  = ((size_t)b * SEQ + qt * 128) * HID + h * HD;
    const size_t baseKV = (size_t)b * SEQ * HID + h * HD;
    const size_t baseVT = (size_t)bhid * HD * SEQ;

    // Stage Q (128 rows x 64 d) into stage-0 region, extract persistent frags
    {
        __nv_bfloat16* sQh = fsm;                  // 128*AT_STR = 2*TILEA
        __nv_bfloat16* sQl = fsm + 2 * TILEA;
        for (int s = tid; s < 1024; s += 256) {
            int r = s >> 3;
            int c8 = (s & 7) * 8;
            *reinterpret_cast<uint4*>(&sQh[r * AT_STR + c8]) =
                *reinterpret_cast<const uint4*>(qh + baseQ + (size_t)r * HID + c8);
            *reinterpret_cast<uint4*>(&sQl[r * AT_STR + c8]) =
                *reinterpret_cast<const uint4*>(ql + baseQ + (size_t)r * HID + c8);
        }
    }
    __syncthreads();

    uint32_t qfh[4][4], qfl[4][4];
    {
        __nv_bfloat16* sQh = fsm;
        __nv_bfloat16* sQl = fsm + 2 * TILEA;
        int row = w * 16 + g;
#pragma unroll
        for (int kc = 0; kc < 4; kc++) {
            int c = kc * 16 + tig * 2;
            qfh[kc][0] = *reinterpret_cast<uint32_t*>(&sQh[row * AT_STR + c]);
            qfh[kc][1] = *reinterpret_cast<uint32_t*>(&sQh[(row + 8) * AT_STR + c]);
            qfh[kc][2] = *reinterpret_cast<uint32_t*>(&sQh[row * AT_STR + c + 8]);
            qfh[kc][3] = *reinterpret_cast<uint32_t*>(&sQh[(row + 8) * AT_STR + c + 8]);
            qfl[kc][0] = *reinterpret_cast<uint32_t*>(&sQl[row * AT_STR + c]);
            qfl[kc][1] = *reinterpret_cast<uint32_t*>(&sQl[(row + 8) * AT_STR + c]);
            qfl[kc][2] = *reinterpret_cast<uint32_t*>(&sQl[row * AT_STR + c + 8]);
            qfl[kc][3] = *reinterpret_cast<uint32_t*>(&sQl[(row + 8) * AT_STR + c + 8]);
        }
    }
    __syncthreads();

    auto issue = [&](int jt, int buf) {
        uint32_t b0 = sbase + (uint32_t)buf * 4 * TILEA * 2;
        const __nv_bfloat16* kbh = kh + baseKV + (size_t)jt * 64 * HID;
        const __nv_bfloat16* kbl = kl + baseKV + (size_t)jt * 64 * HID;
        const __nv_bfloat16* vbh = vhT + baseVT + jt * 64;
        const __nv_bfloat16* vbl = vlT + baseVT + jt * 64;
        for (int s = tid; s < 512; s += 256) {
            int r = s >> 3;
            int c8 = (s & 7) * 8;
            uint32_t doff = (uint32_t)(r * AT_STR + c8) * 2;
            cpa16(b0 + 0u * TILEA * 2 + doff, kbh + (size_t)r * HID + c8);
            cpa16(b0 + 1u * TILEA * 2 + doff, kbl + (size_t)r * HID + c8);
            cpa16(b0 + 2u * TILEA * 2 + doff, vbh + (size_t)r * SEQ + c8);
            cpa16(b0 + 3u * TILEA * 2 + doff, vbl + (size_t)r * SEQ + c8);
        }
        cp_commit();
    };

    float O[8][4];
#pragma unroll
    for (int nf = 0; nf < 8; nf++)
#pragma unroll
        for (int c = 0; c < 4; c++) O[nf][c] = 0.f;
    float m0 = -INFINITY, m1 = -INFINITY, l0 = 0.f, l1 = 0.f;

    const int nt = 2 * qt + 2;   // kv tiles for this block
    issue(0, 0);

    for (int jt = 0; jt < nt; jt++) {
        if (jt < nt - 1) issue(jt + 1, (jt + 1) & 1);
        if (jt < nt - 1) cp_wait<1>(); else cp_wait<0>();
        __syncthreads();

        __nv_bfloat16* sKh = fsm + (size_t)(jt & 1) * 4 * TILEA;
        __nv_bfloat16* sKl = sKh + TILEA;
        __nv_bfloat16* sVh = sKh + 2 * TILEA;
        __nv_bfloat16* sVl = sKh + 3 * TILEA;

        // S = Q K^T (16x64 per warp), 3-pass split
        float S[8][4];
#pragma unroll
        for (int nf = 0; nf < 8; nf++)
#pragma unroll
            for (int c = 0; c < 4; c++) S[nf][c] = 0.f;

#pragma unroll
        for (int nf = 0; nf < 8; nf++) {
            int rowb = nf * 8 + g;
#pragma unroll
            for (int kc = 0; kc < 4; kc++) {
                int c = kc * 16 + tig * 2;
                uint32_t bkh[2], bkl[2];
                bkh[0] = *reinterpret_cast<uint32_t*>(&sKh[rowb * AT_STR + c]);
                bkh[1] = *reinterpret_cast<uint32_t*>(&sKh[rowb * AT_STR + c + 8]);
                bkl[0] = *reinterpret_cast<uint32_t*>(&sKl[rowb * AT_STR + c]);
                bkl[1] = *reinterpret_cast<uint32_t*>(&sKl[rowb * AT_STR + c + 8]);
                MMA16816(S[nf], qfh[kc], bkh);
                MMA16816(S[nf], qfh[kc], bkl);
                MMA16816(S[nf], qfl[kc], bkh);
            }
        }

        // Causal mask (only possible in the last two kv tiles)
        if (jt >= 2 * qt) {
            int qg0 = qt * 128 + w * 16 + g;
            int qg1 = qg0 + 8;
#pragma unroll
            for (int nf = 0; nf < 8; nf++) {
                int jglob = jt * 64 + nf * 8 + tig * 2;
                if (jglob > qg0)     S[nf][0] = -INFINITY;
                if (jglob + 1 > qg0) S[nf][1] = -INFINITY;
                if (jglob > qg1)     S[nf][2] = -INFINITY;
                if (jglob + 1 > qg1) S[nf][3] = -INFINITY;
            }
        }

        // Online softmax (quad shfl)
        float mx0 = -INFINITY, mx1 = -INFINITY;
#pragma unroll
        for (int nf = 0; nf < 8; nf++) {
            mx0 = fmaxf(mx0, fmaxf(S[nf][0], S[nf][1]));
            mx1 = fmaxf(mx1, fmaxf(S[nf][2], S[nf][3]));
        }
        mx0 = fmaxf(mx0, __shfl_xor_sync(0xFFFFFFFF, mx0, 1));
        mx0 = fmaxf(mx0, __shfl_xor_sync(0xFFFFFFFF, mx0, 2));
        mx1 = fmaxf(mx1, __shfl_xor_sync(0xFFFFFFFF, mx1, 1));
        mx1 = fmaxf(mx1, __shfl_xor_sync(0xFFFFFFFF, mx1, 2));
        float nm0 = fmaxf(m0, mx0);
        float nm1 = fmaxf(m1, mx1);
        float corr0 = __expf(m0 - nm0);
        float corr1 = __expf(m1 - nm1);
        m0 = nm0; m1 = nm1;
        float sum0 = 0.f, sum1 = 0.f;
#pragma unroll
        for (int nf = 0; nf < 8; nf++) {
            S[nf][0] = __expf(S[nf][0] - m0); sum0 += S[nf][0];
            S[nf][1] = __expf(S[nf][1] - m0); sum0 += S[nf][1];
            S[nf][2] = __expf(S[nf][2] - m1); sum1 += S[nf][2];
            S[nf][3] = __expf(S[nf][3] - m1); sum1 += S[nf][3];
        }
        sum0 += __shfl_xor_sync(0xFFFFFFFF, sum0, 1);
        sum0 += __shfl_xor_sync(0xFFFFFFFF, sum0, 2);
        sum1 += __shfl_xor_sync(0xFFFFFFFF, sum1, 1);
        sum1 += __shfl_xor_sync(0xFFFFFFFF, sum1, 2);
        l0 = l0 * corr0 + sum0;
        l1 = l1 * corr1 + sum1;
#pragma unroll
        for (int nf = 0; nf < 8; nf++) {
            O[nf][0] *= corr0; O[nf][1] *= corr0;
            O[nf][2] *= corr1; O[nf][3] *= corr1;
        }

        // S (C-frag) -> P A-frags (hi/lo) in registers
        uint32_t aPh[4][4], aPl[4][4];
#pragma unroll
        for (int kc = 0; kc < 4; kc++) {
            split_pack(S[2 * kc][0],     S[2 * kc][1],     aPh[kc][0], aPl[kc][0]);
            split_pack(S[2 * kc][2],     S[2 * kc][3],     aPh[kc][1], aPl[kc][1]);
            split_pack(S[2 * kc + 1][0], S[2 * kc + 1][1], aPh[kc][2], aPl[kc][2]);
            split_pack(S[2 * kc + 1][2], S[2 * kc + 1][3], aPh[kc][3], aPl[kc][3]);
        }

        // O += P @ V (V^T tiles), 3-pass split
#pragma unroll
        for (int nf = 0; nf < 8; nf++) {
            int rowb = nf * 8 + g;
#pragma unroll
            for (int kc = 0; kc < 4; kc++) {
                int c = kc * 16 + tig * 2;
                uint32_t bvh[2], bvl[2];
                bvh[0] = *reinterpret_cast<uint32_t*>(&sVh[rowb * AT_STR + c]);
                bvh[1] = *reinterpret_cast<uint32_t*>(&sVh[rowb * AT_STR + c + 8]);
                bvl[0] = *reinterpret_cast<uint32_t*>(&sVl[rowb * AT_STR + c]);
                bvl[1] = *reinterpret_cast<uint32_t*>(&sVl[rowb * AT_STR + c + 8]);
                MMA16816(O[nf], aPh[kc], bvh);
                MMA16816(O[nf], aPh[kc], bvl);
                MMA16816(O[nf], aPl[kc], bvh);
            }
        }
        __syncthreads();
    }

    // Normalize + split-bf16 write (feeds the output GEMM directly)
    float inv0 = 1.f / l0;
    float inv1 = 1.f / l1;
    int row0 = qt * 128 + w * 16 + g;
#pragma unroll
    for (int nf = 0; nf < 8; nf++) {
        int col = nf * 8 + tig * 2;
        uint32_t hp, lp;
        size_t o0 = ((size_t)b * SEQ + row0) * HID + h * HD + col;
        size_t o1 = ((size_t)b * SEQ + row0 + 8) * HID + h * HD + col;
        split_pack(O[nf][0] * inv0, O[nf][1] * inv0, hp, lp);
        *reinterpret_cast<uint32_t*>(&oh[o0]) = hp;
        *reinterpret_cast<uint32_t*>(&ol[o0]) = lp;
        split_pack(O[nf][2] * inv1, O[nf][3] * inv1, hp, lp);
        *reinterpret_cast<uint32_t*>(&oh[o1]) = hp;
        *reinterpret_cast<uint32_t*>(&ol[o1]) = lp;
    }
}

// ---------------------------------------------------------------------------
// Launch
// ---------------------------------------------------------------------------
extern "C" void kernel_launch(void* const* d_in, const int* in_sizes, int n_in,
                              void* d_out, int out_size) {
    const float* x    = (const float*)d_in[0];
    const float* cosT = (const float*)d_in[1];
    const float* sinT = (const float*)d_in[2];
    const float* wq   = (const float*)d_in[3];
    const float* wk   = (const float*)d_in[4];
    const float* wv   = (const float*)d_in[5];
    const float* wo   = (const float*)d_in[6];
    float* out = (float*)d_out;

    float* v;
    __nv_bfloat16 *xh, *xl, *wh, *wl, *ah, *al;
    __nv_bfloat16 *qhp, *qlp, *khp, *klp, *vhp, *vlp;
    cudaGetSymbolAddress((void**)&v, g_v);
    cudaGetSymbolAddress((void**)&xh, g_xh);
    cudaGetSymbolAddress((void**)&xl, g_xl);
    cudaGetSymbolAddress((void**)&wh, g_wh);
    cudaGetSymbolAddress((void**)&wl, g_wl);
    cudaGetSymbolAddress((void**)&ah, g_ah);
    cudaGetSymbolAddress((void**)&al, g_al);
    cudaGetSymbolAddress((void**)&qhp, g_qh);
    cudaGetSymbolAddress((void**)&qlp, g_ql);
    cudaGetSymbolAddress((void**)&khp, g_kh);
    cudaGetSymbolAddress((void**)&klp, g_kl);
    cudaGetSymbolAddress((void**)&vhp, g_vh);
    cudaGetSymbolAddress((void**)&vlp, g_vl);

    cudaFuncSetAttribute(gemm_mma<0>, cudaFuncAttributeMaxDynamicSharedMemorySize,
                         GEMM_SMEM);
    cudaFuncSetAttribute(gemm_mma<1>, cudaFuncAttributeMaxDynamicSharedMemorySize,
                         GEMM_SMEM);
    cudaFuncSetAttribute(flash_mma, cudaFuncAttributeMaxDynamicSharedMemorySize,
                         FLASH_SMEM);

    // Split inputs to bf16 hi/lo
    int x4 = MROWS * HID / 4;
    int w4 = HID * HID / 4;
    split_kernel<<<(x4 + 255) / 256, 256>>>(x, xh, xl, x4);
    split_kernel<<<(w4 + 255) / 256, 256>>>(wq, wh + 0 * HID * HID, wl + 0 * HID * HID, w4);
    split_kernel<<<(w4 + 255) / 256, 256>>>(wk, wh + 1 * HID * HID, wl + 1 * HID * HID, w4);
    split_kernel<<<(w4 + 255) / 256, 256>>>(wv, wh + 2 * HID * HID, wl + 2 * HID * HID, w4);
    split_kernel<<<(w4 + 255) / 256, 256>>>(wo, wh + 3 * HID * HID, wl + 3 * HID * HID, w4);

    dim3 ggrid(HID / 128, MROWS / 128);   // (8, 64)
    // Q/K: fused rope + scale + split epilogue (no fp32 intermediate)
    gemm_mma<1><<<ggrid, 256, GEMM_SMEM>>>(xh, xl, wh + 0 * HID * HID, wl + 0 * HID * HID,
                                           nullptr, qhp, qlp, cosT, sinT, 0.125f);
    gemm_mma<1><<<ggrid, 256, GEMM_SMEM>>>(xh, xl, wh + 1 * HID * HID, wl + 1 * HID * HID,
                                           nullptr, khp, klp, cosT, sinT, 1.0f);
    // V: fp32 out, then transpose+split
    gemm_mma<0><<<ggrid, 256, GEMM_SMEM>>>(xh, xl, wh + 2 * HID * HID, wl + 2 * HID * HID,
                                           v, nullptr, nullptr, nullptr, nullptr, 1.0f);
    vsplit_t<<<dim3(SEQ / 32, HD / 32, BATCH * NH), dim3(32, 8)>>>(v, vhp, vlp);

    dim3 fgrid(SEQ / 128, BATCH * NH);    // (16, 64)
    flash_mma<<<fgrid, 256, FLASH_SMEM>>>(qhp, qlp, khp, klp, vhp, vlp, ah, al);

    // Output projection reads flash's split output directly
    gemm_mma<0><<<ggrid, 256, GEMM_SMEM>>>(ah, al, wh + 3 * HID * HID, wl + 3 * HID * HID,
                                           out, nullptr, nullptr, nullptr, nullptr, 1.0f);
}